// round 1
// baseline (speedup 1.0000x reference)
#include <cuda_runtime.h>
#include <cstdint>
#include <cstddef>

// ---------------------------------------------------------------------------
// CrossAttention_41497974014052  (sm_103a)
// Pipeline: depthwise3x3 -> pointwise GEMM (TF32 mma) -> per-(b,h) channel
// attention (TF32 mma + smem softmax). fp32 storage, tf32 math, fp32 accum.
// ---------------------------------------------------------------------------

constexpr int Bn = 8, Cn = 256, Hn = 128, Wn = 128;
constexpr int HWn = Hn * Wn;                    // 16384
constexpr size_t CHWn = (size_t)Cn * HWn;       // 4194304
constexpr size_t IMG  = (size_t)Bn * CHWn;      // 33554432

// scratch: depthwise outputs (y) and projected q,k,v
__device__ float g_y[3 * IMG];
__device__ float g_qkv[3 * IMG];

__device__ __forceinline__ float tf32r(float x) {
    uint32_t u;
    asm("cvt.rna.tf32.f32 %0, %1;" : "=r"(u) : "f"(x));
    return __uint_as_float(u);
}

__device__ __forceinline__ void mma8(float d[4], const uint32_t a[4], const uint32_t b[2]) {
    asm volatile(
        "mma.sync.aligned.m16n8k8.row.col.f32.tf32.tf32.f32 "
        "{%0,%1,%2,%3}, {%4,%5,%6,%7}, {%8,%9}, {%0,%1,%2,%3};\n"
        : "+f"(d[0]), "+f"(d[1]), "+f"(d[2]), "+f"(d[3])
        : "r"(a[0]), "r"(a[1]), "r"(a[2]), "r"(a[3]), "r"(b[0]), "r"(b[1]));
}

// ---------------------------------------------------------------------------
// Kernel 1: depthwise 3x3 (SAME, correlation) + bias for q (hidden), k,v (ctx)
// grid: (H, B*C), block: W threads
// ---------------------------------------------------------------------------
__global__ void k_dwconv(const float* __restrict__ hidden, const float* __restrict__ ctx,
                         const float* __restrict__ qw, const float* __restrict__ qb,
                         const float* __restrict__ kw, const float* __restrict__ kb,
                         const float* __restrict__ vw, const float* __restrict__ vb)
{
    int h  = blockIdx.x;
    int bc = blockIdx.y;                 // b*C + c
    int c  = bc & (Cn - 1);
    int w  = threadIdx.x;
    size_t base = (size_t)bc * HWn;
    const float* xh = hidden + base;
    const float* xc = ctx + base;

    float aq = qb[c], ak = kb[c], av = vb[c];
    #pragma unroll
    for (int i = 0; i < 3; i++) {
        int hh = h + i - 1;
        if ((unsigned)hh >= (unsigned)Hn) continue;
        #pragma unroll
        for (int j = 0; j < 3; j++) {
            int ww = w + j - 1;
            if ((unsigned)ww >= (unsigned)Wn) continue;
            int wi = c * 9 + i * 3 + j;
            float xv = xh[hh * Wn + ww];
            float cv = xc[hh * Wn + ww];
            aq += qw[wi] * xv;
            ak += kw[wi] * cv;
            av += vw[wi] * cv;
        }
    }
    size_t o = base + (size_t)h * Wn + w;
    g_y[o]           = tf32r(aq);
    g_y[IMG + o]     = tf32r(ak);
    g_y[2 * IMG + o] = tf32r(av);
}

// ---------------------------------------------------------------------------
// Kernel 2: pointwise conv = GEMM  C[o][s] = sum_c A[o][c] * y[c][s] + bias[o]
// CTA tile 128x128, K=256 in 16-chunks, double-buffered. 256 thr = 8 warps
// (2M x 4N), warp tile 64x32, m16n8k8 tf32.
// grid: (HW/128, 2, 3*8)
// ---------------------------------------------------------------------------
__global__ void __launch_bounds__(256)
k_pointwise(const float* __restrict__ qpw, const float* __restrict__ qpb,
            const float* __restrict__ kpw, const float* __restrict__ kpb,
            const float* __restrict__ vpw, const float* __restrict__ vpb)
{
    __shared__ __align__(16) float As[2][128 * 20];  // [m][k] stride 20
    __shared__ __align__(16) float Bs[2][16 * 136];  // [k][n] stride 136

    int nt = blockIdx.x;
    int mt = blockIdx.y;
    int tb = blockIdx.z;
    int t = tb >> 3, b = tb & 7;
    const float* A    = (t == 0) ? qpw : (t == 1) ? kpw : vpw;
    const float* bias = (t == 0) ? qpb : (t == 1) ? kpb : vpb;
    const float* Bm = g_y  + (size_t)t * IMG + (size_t)b * CHWn;
    float*       Cm = g_qkv + (size_t)t * IMG + (size_t)b * CHWn;
    int n0 = nt * 128, m0 = mt * 128;

    int tid = threadIdx.x;
    int lane = tid & 31, warp = tid >> 5;
    int wm = warp >> 2, wn = warp & 3;
    int g = lane >> 2, tg = lane & 3;

    int mA = tid >> 2, kqA = (tid & 3) * 4;
    int kB = tid >> 5, nqB = (tid & 31) * 4;

    float acc[4][4][4];
    #pragma unroll
    for (int i = 0; i < 4; i++)
        #pragma unroll
        for (int j = 0; j < 4; j++)
            #pragma unroll
            for (int r = 0; r < 4; r++) acc[i][j][r] = 0.f;

    float4 ra[2], rb[2];
    // prologue: chunk 0
    #pragma unroll
    for (int r = 0; r < 2; r++) {
        ra[r] = *(const float4*)(A + (size_t)(m0 + mA + 64 * r) * Cn + kqA);
        rb[r] = *(const float4*)(Bm + (size_t)(kB + 8 * r) * HWn + n0 + nqB);
    }
    #pragma unroll
    for (int r = 0; r < 2; r++) {
        float4 v = ra[r];
        v.x = tf32r(v.x); v.y = tf32r(v.y); v.z = tf32r(v.z); v.w = tf32r(v.w);
        *(float4*)&As[0][(mA + 64 * r) * 20 + kqA] = v;
        *(float4*)&Bs[0][(kB + 8 * r) * 136 + nqB] = rb[r];   // y pre-rounded in K1
    }
    __syncthreads();

    for (int kc = 0; kc < 16; kc++) {
        int cur = kc & 1;
        if (kc < 15) {
            int k0 = (kc + 1) * 16;
            #pragma unroll
            for (int r = 0; r < 2; r++) {
                ra[r] = *(const float4*)(A + (size_t)(m0 + mA + 64 * r) * Cn + k0 + kqA);
                rb[r] = *(const float4*)(Bm + (size_t)(k0 + kB + 8 * r) * HWn + n0 + nqB);
            }
        }
        #pragma unroll
        for (int kk = 0; kk < 16; kk += 8) {
            uint32_t af[4][4], bf[4][2];
            #pragma unroll
            for (int mi = 0; mi < 4; mi++) {
                int m = wm * 64 + mi * 16;
                af[mi][0] = __float_as_uint(As[cur][(m + g    ) * 20 + kk + tg    ]);
                af[mi][1] = __float_as_uint(As[cur][(m + g + 8) * 20 + kk + tg    ]);
                af[mi][2] = __float_as_uint(As[cur][(m + g    ) * 20 + kk + tg + 4]);
                af[mi][3] = __float_as_uint(As[cur][(m + g + 8) * 20 + kk + tg + 4]);
            }
            #pragma unroll
            for (int ni = 0; ni < 4; ni++) {
                int n = wn * 32 + ni * 8;
                bf[ni][0] = __float_as_uint(Bs[cur][(kk + tg    ) * 136 + n + g]);
                bf[ni][1] = __float_as_uint(Bs[cur][(kk + tg + 4) * 136 + n + g]);
            }
            #pragma unroll
            for (int mi = 0; mi < 4; mi++)
                #pragma unroll
                for (int ni = 0; ni < 4; ni++)
                    mma8(acc[mi][ni], af[mi], bf[ni]);
        }
        if (kc < 15) {
            __syncthreads();
            int nxt = cur ^ 1;
            #pragma unroll
            for (int r = 0; r < 2; r++) {
                float4 v = ra[r];
                v.x = tf32r(v.x); v.y = tf32r(v.y); v.z = tf32r(v.z); v.w = tf32r(v.w);
                *(float4*)&As[nxt][(mA + 64 * r) * 20 + kqA] = v;
                *(float4*)&Bs[nxt][(kB + 8 * r) * 136 + nqB] = rb[r];
            }
            __syncthreads();
        }
    }

    // epilogue: +bias, tf32-round (q,k,v feed tf32 attention), fp32 store
    #pragma unroll
    for (int mi = 0; mi < 4; mi++) {
        int m = m0 + wm * 64 + mi * 16 + g;
        float b0v = bias[m], b1v = bias[m + 8];
        #pragma unroll
        for (int ni = 0; ni < 4; ni++) {
            int n = n0 + wn * 32 + ni * 8 + tg * 2;
            float2 v0 = make_float2(tf32r(acc[mi][ni][0] + b0v), tf32r(acc[mi][ni][1] + b0v));
            float2 v1 = make_float2(tf32r(acc[mi][ni][2] + b1v), tf32r(acc[mi][ni][3] + b1v));
            *(float2*)(Cm + (size_t)m * HWn + n)       = v0;
            *(float2*)(Cm + (size_t)(m + 8) * HWn + n) = v1;
        }
    }
}

// ---------------------------------------------------------------------------
// Kernel 3: per-(b,h) attention over channels.
//   S = Q K^T * scale  (NT gemm: both row-major [c|d][w])
//   P = softmax_rows(S),  O = P V   (NN gemm)
// CTA = 1 (b,h) slice, 256 threads, 4 q-tiles of 64 rows.
// smem: Ss[64][264] | Qs[64][20] Ks[256][20] (Vs[16][136] aliases Qs/Ks)
// ---------------------------------------------------------------------------
constexpr int ATTN_SMEM_FLOATS = 64 * 264 + 64 * 20 + 256 * 20;   // 23296
constexpr int ATTN_SMEM_BYTES  = ATTN_SMEM_FLOATS * 4;            // 93184

__global__ void __launch_bounds__(256)
k_attn(float* __restrict__ out)
{
    extern __shared__ __align__(16) float sm[];
    float* Ss = sm;                 // 64 x 264
    float* Qs = sm + 64 * 264;      // 64 x 20
    float* Ks = Qs + 64 * 20;       // 256 x 20
    float* Vs = Qs;                 // 16 x 136 (aliases Qs/Ks region)

    int bh = blockIdx.x;
    int b = bh >> 7, h = bh & 127;
    const float* Qg = g_qkv + (size_t)b * CHWn + (size_t)h * Wn;  // (c,w): Qg[c*HW + w]
    const float* Kg = Qg + IMG;
    const float* Vg = Qg + 2 * IMG;
    float* Og = out + (size_t)b * CHWn + (size_t)h * Wn;

    int tid = threadIdx.x;
    int lane = tid & 31, warp = tid >> 5;
    int g = lane >> 2, tg = lane & 3;
    int wm = warp >> 2, wn = warp & 3;      // 2M x 4N for both gemms
    const float scale = 0.17677669529663687f;   // 1/sqrt(32)

    int mQ = tid >> 2, kqQ = (tid & 3) * 4;     // Qs loads
    int dK = tid >> 2, wqK = (tid & 3) * 4;     // Ks loads
    int kV = tid >> 5, nqV = (tid & 31) * 4;    // Vs loads

    for (int qt = 0; qt < 4; qt++) {
        int c0 = qt * 64;

        // ---- GEMM1: S[64,256] = Qt[64,128] @ K^T, warp tile 32x64 ----
        float acc1[2][8][4];
        #pragma unroll
        for (int i = 0; i < 2; i++)
            #pragma unroll
            for (int j = 0; j < 8; j++)
                #pragma unroll
                for (int r = 0; r < 4; r++) acc1[i][j][r] = 0.f;

        for (int kc = 0; kc < 8; kc++) {
            int k0 = kc * 16;
            __syncthreads();
            *(float4*)&Qs[mQ * 20 + kqQ] =
                *(const float4*)(Qg + (size_t)(c0 + mQ) * HWn + k0 + kqQ);
            #pragma unroll
            for (int r = 0; r < 4; r++)
                *(float4*)&Ks[(dK + 64 * r) * 20 + wqK] =
                    *(const float4*)(Kg + (size_t)(dK + 64 * r) * HWn + k0 + wqK);
            __syncthreads();

            #pragma unroll
            for (int kk = 0; kk < 16; kk += 8) {
                uint32_t af[2][4], bf[8][2];
                #pragma unroll
                for (int mi = 0; mi < 2; mi++) {
                    int m = wm * 32 + mi * 16;
                    af[mi][0] = __float_as_uint(Qs[(m + g    ) * 20 + kk + tg    ]);
                    af[mi][1] = __float_as_uint(Qs[(m + g + 8) * 20 + kk + tg    ]);
                    af[mi][2] = __float_as_uint(Qs[(m + g    ) * 20 + kk + tg + 4]);
                    af[mi][3] = __float_as_uint(Qs[(m + g + 8) * 20 + kk + tg + 4]);
                }
                #pragma unroll
                for (int ni = 0; ni < 8; ni++) {
                    int n = wn * 64 + ni * 8;
                    bf[ni][0] = __float_as_uint(Ks[(n + g) * 20 + kk + tg    ]);
                    bf[ni][1] = __float_as_uint(Ks[(n + g) * 20 + kk + tg + 4]);
                }
                #pragma unroll
                for (int mi = 0; mi < 2; mi++)
                    #pragma unroll
                    for (int ni = 0; ni < 8; ni++)
                        mma8(acc1[mi][ni], af[mi], bf[ni]);
            }
        }

        // scale + write S tile to smem
        #pragma unroll
        for (int mi = 0; mi < 2; mi++) {
            int m = wm * 32 + mi * 16 + g;
            #pragma unroll
            for (int ni = 0; ni < 8; ni++) {
                int n = wn * 64 + ni * 8 + tg * 2;
                *(float2*)&Ss[m * 264 + n] =
                    make_float2(acc1[mi][ni][0] * scale, acc1[mi][ni][1] * scale);
                *(float2*)&Ss[(m + 8) * 264 + n] =
                    make_float2(acc1[mi][ni][2] * scale, acc1[mi][ni][3] * scale);
            }
        }
        __syncthreads();

        // ---- softmax over 256 cols, one warp per row, 8 rows per warp ----
        #pragma unroll 1
        for (int rr = 0; rr < 8; rr++) {
            int r = warp * 8 + rr;
            float v[8];
            float mx = -1e30f;
            #pragma unroll
            for (int i = 0; i < 8; i++) {
                v[i] = Ss[r * 264 + lane + 32 * i];
                mx = fmaxf(mx, v[i]);
            }
            #pragma unroll
            for (int o = 16; o > 0; o >>= 1)
                mx = fmaxf(mx, __shfl_xor_sync(0xffffffffu, mx, o));
            float s = 0.f;
            #pragma unroll
            for (int i = 0; i < 8; i++) { v[i] = __expf(v[i] - mx); s += v[i]; }
            #pragma unroll
            for (int o = 16; o > 0; o >>= 1)
                s += __shfl_xor_sync(0xffffffffu, s, o);
            float inv = 1.f / s;
            #pragma unroll
            for (int i = 0; i < 8; i++)
                Ss[r * 264 + lane + 32 * i] = tf32r(v[i] * inv);
        }
        __syncthreads();

        // ---- GEMM2: O[64,128] = P[64,256] @ V[256,128], warp tile 32x32 ----
        float acc2[2][4][4];
        #pragma unroll
        for (int i = 0; i < 2; i++)
            #pragma unroll
            for (int j = 0; j < 4; j++)
                #pragma unroll
                for (int r = 0; r < 4; r++) acc2[i][j][r] = 0.f;

        for (int kc = 0; kc < 16; kc++) {
            int k0 = kc * 16;
            __syncthreads();
            #pragma unroll
            for (int r = 0; r < 2; r++)
                *(float4*)&Vs[(kV + 8 * r) * 136 + nqV] =
                    *(const float4*)(Vg + (size_t)(k0 + kV + 8 * r) * HWn + nqV);
            __syncthreads();

            #pragma unroll
            for (int kk = 0; kk < 16; kk += 8) {
                uint32_t af[2][4], bf[4][2];
                #pragma unroll
                for (int mi = 0; mi < 2; mi++) {
                    int m = wm * 32 + mi * 16;
                    af[mi][0] = __float_as_uint(Ss[(m + g    ) * 264 + k0 + kk + tg    ]);
                    af[mi][1] = __float_as_uint(Ss[(m + g + 8) * 264 + k0 + kk + tg    ]);
                    af[mi][2] = __float_as_uint(Ss[(m + g    ) * 264 + k0 + kk + tg + 4]);
                    af[mi][3] = __float_as_uint(Ss[(m + g + 8) * 264 + k0 + kk + tg + 4]);
                }
                #pragma unroll
                for (int ni = 0; ni < 4; ni++) {
                    int n = wn * 32 + ni * 8;
                    bf[ni][0] = __float_as_uint(Vs[(kk + tg    ) * 136 + n + g]);
                    bf[ni][1] = __float_as_uint(Vs[(kk + tg + 4) * 136 + n + g]);
                }
                #pragma unroll
                for (int mi = 0; mi < 2; mi++)
                    #pragma unroll
                    for (int ni = 0; ni < 4; ni++)
                        mma8(acc2[mi][ni], af[mi], bf[ni]);
            }
        }

        // epilogue: fp32 store to out[b, c, h, w]
        #pragma unroll
        for (int mi = 0; mi < 2; mi++) {
            int m = wm * 32 + mi * 16 + g;
            #pragma unroll
            for (int ni = 0; ni < 4; ni++) {
                int n = wn * 32 + ni * 8 + tg * 2;
                *(float2*)(Og + (size_t)(c0 + m) * HWn + n) =
                    make_float2(acc2[mi][ni][0], acc2[mi][ni][1]);
                *(float2*)(Og + (size_t)(c0 + m + 8) * HWn + n) =
                    make_float2(acc2[mi][ni][2], acc2[mi][ni][3]);
            }
        }
        // next qt's GEMM1 loop begins with __syncthreads() before touching Qs/Ks
    }
}

// ---------------------------------------------------------------------------
extern "C" void kernel_launch(void* const* d_in, const int* in_sizes, int n_in,
                              void* d_out, int out_size)
{
    (void)in_sizes; (void)n_in; (void)out_size;
    const float* hidden = (const float*)d_in[0];
    const float* ctx    = (const float*)d_in[1];
    const float* qdw = (const float*)d_in[2];
    const float* qdb = (const float*)d_in[3];
    const float* qpw = (const float*)d_in[4];
    const float* qpb = (const float*)d_in[5];
    const float* kdw = (const float*)d_in[6];
    const float* kdb = (const float*)d_in[7];
    const float* kpw = (const float*)d_in[8];
    const float* kpb = (const float*)d_in[9];
    const float* vdw = (const float*)d_in[10];
    const float* vdb = (const float*)d_in[11];
    const float* vpw = (const float*)d_in[12];
    const float* vpb = (const float*)d_in[13];
    float* out = (float*)d_out;

    k_dwconv<<<dim3(Hn, Bn * Cn), Wn>>>(hidden, ctx, qdw, qdb, kdw, kdb, vdw, vdb);
    k_pointwise<<<dim3(HWn / 128, 2, 24), 256>>>(qpw, qpb, kpw, kpb, vpw, vpb);
    cudaFuncSetAttribute(k_attn, cudaFuncAttributeMaxDynamicSharedMemorySize, ATTN_SMEM_BYTES);
    k_attn<<<Bn * Hn, 256, ATTN_SMEM_BYTES>>>(out);
}

// round 4
// speedup vs baseline: 1.0853x; 1.0853x over previous
#include <cuda_runtime.h>
#include <cstdint>
#include <cstddef>

// ---------------------------------------------------------------------------
// CrossAttention_41497974014052  (sm_103a)
// Pipeline: depthwise3x3 (smem-tiled) -> pointwise GEMM (TF32 mma) ->
// per-(b,h) channel attention, 128-row q-tiles (TF32 mma + smem softmax).
// fp32 storage, tf32 math, fp32 accum.
// ---------------------------------------------------------------------------

constexpr int Bn = 8, Cn = 256, Hn = 128, Wn = 128;
constexpr int HWn = Hn * Wn;                    // 16384
constexpr size_t CHWn = (size_t)Cn * HWn;       // 4194304
constexpr size_t IMG  = (size_t)Bn * CHWn;      // 33554432

// scratch: depthwise outputs (y) and projected q,k,v
__device__ float g_y[3 * IMG];
__device__ float g_qkv[3 * IMG];

__device__ __forceinline__ float tf32r(float x) {
    uint32_t u;
    asm("cvt.rna.tf32.f32 %0, %1;" : "=r"(u) : "f"(x));
    return __uint_as_float(u);
}

__device__ __forceinline__ void mma8(float d[4], const uint32_t a[4], const uint32_t b[2]) {
    asm volatile(
        "mma.sync.aligned.m16n8k8.row.col.f32.tf32.tf32.f32 "
        "{%0,%1,%2,%3}, {%4,%5,%6,%7}, {%8,%9}, {%0,%1,%2,%3};\n"
        : "+f"(d[0]), "+f"(d[1]), "+f"(d[2]), "+f"(d[3])
        : "r"(a[0]), "r"(a[1]), "r"(a[2]), "r"(a[3]), "r"(b[0]), "r"(b[1]));
}

// ---------------------------------------------------------------------------
// Kernel 1: depthwise 3x3 (SAME) + bias, smem-tiled with sliding row window.
// grid: (H/16, B*C), block 256. Each CTA: one (b,c) plane, 16 rows x 128 cols.
// ---------------------------------------------------------------------------
__global__ void __launch_bounds__(256)
k_dwconv(const float* __restrict__ hidden, const float* __restrict__ ctx,
         const float* __restrict__ qw, const float* __restrict__ qb,
         const float* __restrict__ kw, const float* __restrict__ kb,
         const float* __restrict__ vw, const float* __restrict__ vb)
{
    __shared__ float shH[18][132];
    __shared__ float shC[18][132];

    int h0 = blockIdx.x * 16;
    int bc = blockIdx.y;                 // b*C + c
    int c  = bc & (Cn - 1);
    int tid = threadIdx.x;
    size_t base = (size_t)bc * HWn;
    const float* xh = hidden + base;
    const float* xc = ctx + base;

    // load 18 rows x 130 cols (halo), zero-padded
    for (int idx = tid; idx < 18 * 130; idx += 256) {
        int r = idx / 130, ci = idx - r * 130;
        int hh = h0 + r - 1, ww = ci - 1;
        bool ok = ((unsigned)hh < (unsigned)Hn) & ((unsigned)ww < (unsigned)Wn);
        float vh = 0.f, vc = 0.f;
        if (ok) {
            int o = hh * Wn + ww;
            vh = xh[o]; vc = xc[o];
        }
        shH[r][ci] = vh;
        shC[r][ci] = vc;
    }

    // per-channel weights (uniform across block -> broadcast loads)
    float wq[9], wk[9], wv[9];
    #pragma unroll
    for (int i = 0; i < 9; i++) {
        wq[i] = qw[c * 9 + i]; wk[i] = kw[c * 9 + i]; wv[i] = vw[c * 9 + i];
    }
    float bq = qb[c], bk = kb[c], bv = vb[c];
    __syncthreads();

    int w  = tid & 127;
    int rh = tid >> 7;          // 0..1 -> rows rh*8 .. rh*8+7
    int rb = rh * 8;

    float A0[3], A1[3], A2[3], B0[3], B1[3], B2[3];
    #pragma unroll
    for (int j = 0; j < 3; j++) {
        A0[j] = shH[rb][w + j];     A1[j] = shH[rb + 1][w + j];
        B0[j] = shC[rb][w + j];     B1[j] = shC[rb + 1][w + j];
    }

    #pragma unroll
    for (int rr = 0; rr < 8; rr++) {
        #pragma unroll
        for (int j = 0; j < 3; j++) {
            A2[j] = shH[rb + rr + 2][w + j];
            B2[j] = shC[rb + rr + 2][w + j];
        }
        float aq = bq, ak = bk, av = bv;
        #pragma unroll
        for (int j = 0; j < 3; j++) {
            aq += wq[j] * A0[j] + wq[3 + j] * A1[j] + wq[6 + j] * A2[j];
            ak += wk[j] * B0[j] + wk[3 + j] * B1[j] + wk[6 + j] * B2[j];
            av += wv[j] * B0[j] + wv[3 + j] * B1[j] + wv[6 + j] * B2[j];
        }
        size_t o = base + (size_t)(h0 + rb + rr) * Wn + w;
        g_y[o]           = tf32r(aq);
        g_y[IMG + o]     = tf32r(ak);
        g_y[2 * IMG + o] = tf32r(av);
        #pragma unroll
        for (int j = 0; j < 3; j++) {
            A0[j] = A1[j]; A1[j] = A2[j];
            B0[j] = B1[j]; B1[j] = B2[j];
        }
    }
}

// ---------------------------------------------------------------------------
// Kernel 2: pointwise conv = GEMM  C[o][s] = sum_c A[o][c] * y[c][s] + bias[o]
// CTA tile 128x128, K=256 in 16-chunks, double-buffered. 256 thr = 8 warps
// (2M x 4N), warp tile 64x32, m16n8k8 tf32.
// grid: (2, HW/128, 3*8) -- mt innermost so both m-tiles of a column stripe
// share the B read through L2.
// ---------------------------------------------------------------------------
__global__ void __launch_bounds__(256)
k_pointwise(const float* __restrict__ qpw, const float* __restrict__ qpb,
            const float* __restrict__ kpw, const float* __restrict__ kpb,
            const float* __restrict__ vpw, const float* __restrict__ vpb)
{
    __shared__ __align__(16) float As[2][128 * 20];  // [m][k] stride 20
    __shared__ __align__(16) float Bs[2][16 * 136];  // [k][n] stride 136

    int mt = blockIdx.x;
    int nt = blockIdx.y;
    int tb = blockIdx.z;
    int t = tb >> 3, b = tb & 7;
    const float* A    = (t == 0) ? qpw : (t == 1) ? kpw : vpw;
    const float* bias = (t == 0) ? qpb : (t == 1) ? kpb : vpb;
    const float* Bm = g_y  + (size_t)t * IMG + (size_t)b * CHWn;
    float*       Cm = g_qkv + (size_t)t * IMG + (size_t)b * CHWn;
    int n0 = nt * 128, m0 = mt * 128;

    int tid = threadIdx.x;
    int lane = tid & 31, warp = tid >> 5;
    int wm = warp >> 2, wn = warp & 3;
    int g = lane >> 2, tg = lane & 3;

    int mA = tid >> 2, kqA = (tid & 3) * 4;
    int kB = tid >> 5, nqB = (tid & 31) * 4;

    float acc[4][4][4];
    #pragma unroll
    for (int i = 0; i < 4; i++)
        #pragma unroll
        for (int j = 0; j < 4; j++)
            #pragma unroll
            for (int r = 0; r < 4; r++) acc[i][j][r] = 0.f;

    float4 ra[2], rb[2];
    #pragma unroll
    for (int r = 0; r < 2; r++) {
        ra[r] = *(const float4*)(A + (size_t)(m0 + mA + 64 * r) * Cn + kqA);
        rb[r] = *(const float4*)(Bm + (size_t)(kB + 8 * r) * HWn + n0 + nqB);
    }
    #pragma unroll
    for (int r = 0; r < 2; r++) {
        float4 v = ra[r];
        v.x = tf32r(v.x); v.y = tf32r(v.y); v.z = tf32r(v.z); v.w = tf32r(v.w);
        *(float4*)&As[0][(mA + 64 * r) * 20 + kqA] = v;
        *(float4*)&Bs[0][(kB + 8 * r) * 136 + nqB] = rb[r];   // y pre-rounded in K1
    }
    __syncthreads();

    for (int kc = 0; kc < 16; kc++) {
        int cur = kc & 1;
        if (kc < 15) {
            int k0 = (kc + 1) * 16;
            #pragma unroll
            for (int r = 0; r < 2; r++) {
                ra[r] = *(const float4*)(A + (size_t)(m0 + mA + 64 * r) * Cn + k0 + kqA);
                rb[r] = *(const float4*)(Bm + (size_t)(k0 + kB + 8 * r) * HWn + n0 + nqB);
            }
        }
        #pragma unroll
        for (int kk = 0; kk < 16; kk += 8) {
            uint32_t af[4][4], bf[4][2];
            #pragma unroll
            for (int mi = 0; mi < 4; mi++) {
                int m = wm * 64 + mi * 16;
                af[mi][0] = __float_as_uint(As[cur][(m + g    ) * 20 + kk + tg    ]);
                af[mi][1] = __float_as_uint(As[cur][(m + g + 8) * 20 + kk + tg    ]);
                af[mi][2] = __float_as_uint(As[cur][(m + g    ) * 20 + kk + tg + 4]);
                af[mi][3] = __float_as_uint(As[cur][(m + g + 8) * 20 + kk + tg + 4]);
            }
            #pragma unroll
            for (int ni = 0; ni < 4; ni++) {
                int n = wn * 32 + ni * 8;
                bf[ni][0] = __float_as_uint(Bs[cur][(kk + tg    ) * 136 + n + g]);
                bf[ni][1] = __float_as_uint(Bs[cur][(kk + tg + 4) * 136 + n + g]);
            }
            #pragma unroll
            for (int mi = 0; mi < 4; mi++)
                #pragma unroll
                for (int ni = 0; ni < 4; ni++)
                    mma8(acc[mi][ni], af[mi], bf[ni]);
        }
        if (kc < 15) {
            __syncthreads();
            int nxt = cur ^ 1;
            #pragma unroll
            for (int r = 0; r < 2; r++) {
                float4 v = ra[r];
                v.x = tf32r(v.x); v.y = tf32r(v.y); v.z = tf32r(v.z); v.w = tf32r(v.w);
                *(float4*)&As[nxt][(mA + 64 * r) * 20 + kqA] = v;
                *(float4*)&Bs[nxt][(kB + 8 * r) * 136 + nqB] = rb[r];
            }
            __syncthreads();
        }
    }

    // epilogue: +bias, tf32-round (q,k,v feed tf32 attention), fp32 store
    #pragma unroll
    for (int mi = 0; mi < 4; mi++) {
        int m = m0 + wm * 64 + mi * 16 + g;
        float b0v = bias[m], b1v = bias[m + 8];
        #pragma unroll
        for (int ni = 0; ni < 4; ni++) {
            int n = n0 + wn * 32 + ni * 8 + tg * 2;
            float2 v0 = make_float2(tf32r(acc[mi][ni][0] + b0v), tf32r(acc[mi][ni][1] + b0v));
            float2 v1 = make_float2(tf32r(acc[mi][ni][2] + b1v), tf32r(acc[mi][ni][3] + b1v));
            *(float2*)(Cm + (size_t)m * HWn + n)       = v0;
            *(float2*)(Cm + (size_t)(m + 8) * HWn + n) = v1;
        }
    }
}

// ---------------------------------------------------------------------------
// Kernel 3: per-(b,h) attention over channels.
//   S = Q K^T * scale  (NT gemm), P = softmax_rows(S), O = P V (NN gemm)
// CTA = 1 (b,h) slice, 512 threads (16 warps), 2 q-tiles of 128 rows.
// smem: Ss[128][264] | Qs[128][20] Ks[256][20] (Vs[16][136] aliases Qs/Ks)
// ---------------------------------------------------------------------------
constexpr int ATTN_SMEM_FLOATS = 128 * 264 + 128 * 20 + 256 * 20;  // 41472
constexpr int ATTN_SMEM_BYTES  = ATTN_SMEM_FLOATS * 4;             // 165888

__global__ void __launch_bounds__(512)
k_attn(float* __restrict__ out)
{
    extern __shared__ __align__(16) float sm[];
    float* Ss = sm;                  // 128 x 264
    float* Qs = sm + 128 * 264;      // 128 x 20
    float* Ks = Qs + 128 * 20;       // 256 x 20
    float* Vs = Qs;                  // 16 x 136 (aliases Qs/Ks region)

    int bh = blockIdx.x;
    int b = bh >> 7, h = bh & 127;
    const float* Qg = g_qkv + (size_t)b * CHWn + (size_t)h * Wn;  // Qg[c*HW + w]
    const float* Kg = Qg + IMG;
    const float* Vg = Qg + 2 * IMG;
    float* Og = out + (size_t)b * CHWn + (size_t)h * Wn;

    int tid = threadIdx.x;
    int lane = tid & 31, warp = tid >> 5;
    int g = lane >> 2, tg = lane & 3;
    int wm = warp >> 2, wn = warp & 3;      // 4M x 4N warps
    const float scale = 0.17677669529663687f;   // 1/sqrt(32)

    int mQ = tid >> 2, kqQ = (tid & 3) * 4;     // Qs loads (128 x 16)
    int dK = tid >> 2, wqK = (tid & 3) * 4;     // Ks loads (256 x 16, 2 rows/thr)
    int kV = tid >> 5, nqV = (tid & 31) * 4;    // Vs loads (16 x 128)

    for (int qt = 0; qt < 2; qt++) {
        int c0 = qt * 128;

        // ---- GEMM1: S[128,256] = Qt[128,128] @ K^T, warp tile 32x64 ----
        float acc1[2][8][4];
        #pragma unroll
        for (int i = 0; i < 2; i++)
            #pragma unroll
            for (int j = 0; j < 8; j++)
                #pragma unroll
                for (int r = 0; r < 4; r++) acc1[i][j][r] = 0.f;

        for (int kc = 0; kc < 8; kc++) {
            int k0 = kc * 16;
            __syncthreads();
            *(float4*)&Qs[mQ * 20 + kqQ] =
                *(const float4*)(Qg + (size_t)(c0 + mQ) * HWn + k0 + kqQ);
            #pragma unroll
            for (int r = 0; r < 2; r++)
                *(float4*)&Ks[(dK + 128 * r) * 20 + wqK] =
                    *(const float4*)(Kg + (size_t)(dK + 128 * r) * HWn + k0 + wqK);
            __syncthreads();

            #pragma unroll
            for (int kk = 0; kk < 16; kk += 8) {
                uint32_t af[2][4], bf[8][2];
                #pragma unroll
                for (int mi = 0; mi < 2; mi++) {
                    int m = wm * 32 + mi * 16;
                    af[mi][0] = __float_as_uint(Qs[(m + g    ) * 20 + kk + tg    ]);
                    af[mi][1] = __float_as_uint(Qs[(m + g + 8) * 20 + kk + tg    ]);
                    af[mi][2] = __float_as_uint(Qs[(m + g    ) * 20 + kk + tg + 4]);
                    af[mi][3] = __float_as_uint(Qs[(m + g + 8) * 20 + kk + tg + 4]);
                }
                #pragma unroll
                for (int ni = 0; ni < 8; ni++) {
                    int n = wn * 64 + ni * 8;
                    bf[ni][0] = __float_as_uint(Ks[(n + g) * 20 + kk + tg    ]);
                    bf[ni][1] = __float_as_uint(Ks[(n + g) * 20 + kk + tg + 4]);
                }
                #pragma unroll
                for (int mi = 0; mi < 2; mi++)
                    #pragma unroll
                    for (int ni = 0; ni < 8; ni++)
                        mma8(acc1[mi][ni], af[mi], bf[ni]);
            }
        }

        // scale + write S tile to smem
        #pragma unroll
        for (int mi = 0; mi < 2; mi++) {
            int m = wm * 32 + mi * 16 + g;
            #pragma unroll
            for (int ni = 0; ni < 8; ni++) {
                int n = wn * 64 + ni * 8 + tg * 2;
                *(float2*)&Ss[m * 264 + n] =
                    make_float2(acc1[mi][ni][0] * scale, acc1[mi][ni][1] * scale);
                *(float2*)&Ss[(m + 8) * 264 + n] =
                    make_float2(acc1[mi][ni][2] * scale, acc1[mi][ni][3] * scale);
            }
        }
        __syncthreads();

        // ---- softmax over 256 cols, one warp per row, 8 rows per warp ----
        #pragma unroll 1
        for (int rr = 0; rr < 8; rr++) {
            int r = warp * 8 + rr;
            float v[8];
            float mx = -1e30f;
            #pragma unroll
            for (int i = 0; i < 8; i++) {
                v[i] = Ss[r * 264 + lane + 32 * i];
                mx = fmaxf(mx, v[i]);
            }
            #pragma unroll
            for (int o = 16; o > 0; o >>= 1)
                mx = fmaxf(mx, __shfl_xor_sync(0xffffffffu, mx, o));
            float s = 0.f;
            #pragma unroll
            for (int i = 0; i < 8; i++) { v[i] = __expf(v[i] - mx); s += v[i]; }
            #pragma unroll
            for (int o = 16; o > 0; o >>= 1)
                s += __shfl_xor_sync(0xffffffffu, s, o);
            float inv = 1.f / s;
            #pragma unroll
            for (int i = 0; i < 8; i++)
                Ss[r * 264 + lane + 32 * i] = tf32r(v[i] * inv);
        }
        __syncthreads();

        // ---- GEMM2: O[128,128] = P[128,256] @ V[256,128], warp tile 32x32 ----
        float acc2[2][4][4];
        #pragma unroll
        for (int i = 0; i < 2; i++)
            #pragma unroll
            for (int j = 0; j < 4; j++)
                #pragma unroll
                for (int r = 0; r < 4; r++) acc2[i][j][r] = 0.f;

        for (int kc = 0; kc < 16; kc++) {
            int k0 = kc * 16;
            __syncthreads();
            *(float4*)&Vs[kV * 136 + nqV] =
                *(const float4*)(Vg + (size_t)(k0 + kV) * HWn + nqV);
            __syncthreads();

            #pragma unroll
            for (int kk = 0; kk < 16; kk += 8) {
                uint32_t af[2][4], bf[4][2];
                #pragma unroll
                for (int mi = 0; mi < 2; mi++) {
                    int m = wm * 32 + mi * 16;
                    af[mi][0] = __float_as_uint(Ss[(m + g    ) * 264 + k0 + kk + tg    ]);
                    af[mi][1] = __float_as_uint(Ss[(m + g + 8) * 264 + k0 + kk + tg    ]);
                    af[mi][2] = __float_as_uint(Ss[(m + g    ) * 264 + k0 + kk + tg + 4]);
                    af[mi][3] = __float_as_uint(Ss[(m + g + 8) * 264 + k0 + kk + tg + 4]);
                }
                #pragma unroll
                for (int ni = 0; ni < 4; ni++) {
                    int n = wn * 32 + ni * 8;
                    bf[ni][0] = __float_as_uint(Vs[(kk + tg    ) * 136 + n + g]);
                    bf[ni][1] = __float_as_uint(Vs[(kk + tg + 4) * 136 + n + g]);
                }
                #pragma unroll
                for (int mi = 0; mi < 2; mi++)
                    #pragma unroll
                    for (int ni = 0; ni < 4; ni++)
                        mma8(acc2[mi][ni], af[mi], bf[ni]);
            }
        }

        // epilogue: fp32 store to out[b, c, h, w]
        #pragma unroll
        for (int mi = 0; mi < 2; mi++) {
            int m = wm * 32 + mi * 16 + g;
            #pragma unroll
            for (int ni = 0; ni < 4; ni++) {
                int n = wn * 32 + ni * 8 + tg * 2;
                *(float2*)(Og + (size_t)(c0 + m) * HWn + n) =
                    make_float2(acc2[mi][ni][0], acc2[mi][ni][1]);
                *(float2*)(Og + (size_t)(c0 + m + 8) * HWn + n) =
                    make_float2(acc2[mi][ni][2], acc2[mi][ni][3]);
            }
        }
        // next qt's GEMM1 loop begins with __syncthreads() before touching Qs/Ks
    }
}

// ---------------------------------------------------------------------------
extern "C" void kernel_launch(void* const* d_in, const int* in_sizes, int n_in,
                              void* d_out, int out_size)
{
    (void)in_sizes; (void)n_in; (void)out_size;
    const float* hidden = (const float*)d_in[0];
    const float* ctx    = (const float*)d_in[1];
    const float* qdw = (const float*)d_in[2];
    const float* qdb = (const float*)d_in[3];
    const float* qpw = (const float*)d_in[4];
    const float* qpb = (const float*)d_in[5];
    const float* kdw = (const float*)d_in[6];
    const float* kdb = (const float*)d_in[7];
    const float* kpw = (const float*)d_in[8];
    const float* kpb = (const float*)d_in[9];
    const float* vdw = (const float*)d_in[10];
    const float* vdb = (const float*)d_in[11];
    const float* vpw = (const float*)d_in[12];
    const float* vpb = (const float*)d_in[13];
    float* out = (float*)d_out;

    k_dwconv<<<dim3(Hn / 16, Bn * Cn), 256>>>(hidden, ctx, qdw, qdb, kdw, kdb, vdw, vdb);
    k_pointwise<<<dim3(2, HWn / 128, 24), 256>>>(qpw, qpb, kpw, kpb, vpw, vpb);
    cudaFuncSetAttribute(k_attn, cudaFuncAttributeMaxDynamicSharedMemorySize, ATTN_SMEM_BYTES);
    k_attn<<<Bn * Hn, 512, ATTN_SMEM_BYTES>>>(out);
}

// round 9
// speedup vs baseline: 1.4310x; 1.3185x over previous
#include <cuda_runtime.h>
#include <cuda_fp16.h>
#include <cstdint>
#include <cstddef>

// ---------------------------------------------------------------------------
// CrossAttention_41497974014052  (sm_103a, legacy mma path)
// K1: depthwise3x3 (smem-tiled) -> half
// K2: pointwise GEMM, fp16 m16n8k16 mma (fp32 accum) -> half
// K3: per-(b,h) channel attention, fp16 mma + fp32 smem softmax -> fp32 out
// ---------------------------------------------------------------------------

constexpr int Bn = 8, Cn = 256, Hn = 128, Wn = 128;
constexpr int HWn = Hn * Wn;                    // 16384
constexpr size_t CHWn = (size_t)Cn * HWn;       // 4194304
constexpr size_t IMG  = (size_t)Bn * CHWn;      // 33554432

__device__ __half g_y[3 * IMG];
__device__ __half g_qkv[3 * IMG];

__device__ __forceinline__ uint32_t f2h2(float a, float b) {
    __half2 h = __floats2half2_rn(a, b);
    return *reinterpret_cast<uint32_t*>(&h);
}
__device__ __forceinline__ uint32_t smem_u32(const void* p) {
    uint32_t a;
    asm("{ .reg .u64 t; cvta.to.shared.u64 t, %1; cvt.u32.u64 %0, t; }" : "=r"(a) : "l"(p));
    return a;
}

// fp16 mma, fp32 accumulate
__device__ __forceinline__ void mma16(float d[4], const uint32_t a[4], const uint32_t b[2]) {
    asm volatile(
        "mma.sync.aligned.m16n8k16.row.col.f32.f16.f16.f32 "
        "{%0,%1,%2,%3}, {%4,%5,%6,%7}, {%8,%9}, {%0,%1,%2,%3};\n"
        : "+f"(d[0]), "+f"(d[1]), "+f"(d[2]), "+f"(d[3])
        : "r"(a[0]), "r"(a[1]), "r"(a[2]), "r"(a[3]), "r"(b[0]), "r"(b[1]));
}

// ldmatrix x4 transposed (for B operands stored row-major [k][n])
__device__ __forceinline__ void ldsm4t(uint32_t& r0, uint32_t& r1, uint32_t& r2, uint32_t& r3,
                                       uint32_t addr) {
    asm volatile("ldmatrix.sync.aligned.m8n8.x4.trans.shared.b16 {%0,%1,%2,%3}, [%4];"
                 : "=r"(r0), "=r"(r1), "=r"(r2), "=r"(r3) : "r"(addr));
}

// ---------------------------------------------------------------------------
// Kernel 1: depthwise 3x3 (SAME) + bias, smem-tiled sliding row window.
// grid (H/16, B*C), 256 threads.
// ---------------------------------------------------------------------------
__global__ void __launch_bounds__(256)
k_dwconv(const float* __restrict__ hidden, const float* __restrict__ ctx,
         const float* __restrict__ qw, const float* __restrict__ qb,
         const float* __restrict__ kw, const float* __restrict__ kb,
         const float* __restrict__ vw, const float* __restrict__ vb)
{
    __shared__ float shH[18][132];
    __shared__ float shC[18][132];

    int h0 = blockIdx.x * 16;
    int bc = blockIdx.y;
    int c  = bc & (Cn - 1);
    int tid = threadIdx.x;
    size_t base = (size_t)bc * HWn;
    const float* xh = hidden + base;
    const float* xc = ctx + base;

    for (int idx = tid; idx < 18 * 130; idx += 256) {
        int r = idx / 130, ci = idx - r * 130;
        int hh = h0 + r - 1, ww = ci - 1;
        bool ok = ((unsigned)hh < (unsigned)Hn) & ((unsigned)ww < (unsigned)Wn);
        float vh = 0.f, vc = 0.f;
        if (ok) { int o = hh * Wn + ww; vh = xh[o]; vc = xc[o]; }
        shH[r][ci] = vh;
        shC[r][ci] = vc;
    }

    float wq[9], wk[9], wv[9];
    #pragma unroll
    for (int i = 0; i < 9; i++) {
        wq[i] = qw[c * 9 + i]; wk[i] = kw[c * 9 + i]; wv[i] = vw[c * 9 + i];
    }
    float bq = qb[c], bk = kb[c], bv = vb[c];
    __syncthreads();

    int w  = tid & 127;
    int rb = (tid >> 7) * 8;

    float A0[3], A1[3], A2[3], B0[3], B1[3], B2[3];
    #pragma unroll
    for (int j = 0; j < 3; j++) {
        A0[j] = shH[rb][w + j];     A1[j] = shH[rb + 1][w + j];
        B0[j] = shC[rb][w + j];     B1[j] = shC[rb + 1][w + j];
    }

    #pragma unroll
    for (int rr = 0; rr < 8; rr++) {
        #pragma unroll
        for (int j = 0; j < 3; j++) {
            A2[j] = shH[rb + rr + 2][w + j];
            B2[j] = shC[rb + rr + 2][w + j];
        }
        float aq = bq, ak = bk, av = bv;
        #pragma unroll
        for (int j = 0; j < 3; j++) {
            aq += wq[j] * A0[j] + wq[3 + j] * A1[j] + wq[6 + j] * A2[j];
            ak += wk[j] * B0[j] + wk[3 + j] * B1[j] + wk[6 + j] * B2[j];
            av += wv[j] * B0[j] + wv[3 + j] * B1[j] + wv[6 + j] * B2[j];
        }
        size_t o = base + (size_t)(h0 + rb + rr) * Wn + w;
        g_y[o]           = __float2half_rn(aq);
        g_y[IMG + o]     = __float2half_rn(ak);
        g_y[2 * IMG + o] = __float2half_rn(av);
        #pragma unroll
        for (int j = 0; j < 3; j++) {
            A0[j] = A1[j]; A1[j] = A2[j];
            B0[j] = B1[j]; B1[j] = B2[j];
        }
    }
}

// ---------------------------------------------------------------------------
// Kernel 2: pointwise GEMM  D[o][s] = sum_c W[o][c] * y[c][s] + bias[o]
// fp16 m16n8k16, CTA 128x128, K=256 in chunks of 32, double-buffered.
// 256 thr = 8 warps (2M x 4N), warp tile 64x32.
// A frags: direct half2 loads from As[m][k] (pitch 40).
// B frags: ldmatrix.x4.trans from Bs[k][n] (pitch 136).
// grid (2, 128, 24)
// ---------------------------------------------------------------------------
__global__ void __launch_bounds__(256)
k_pointwise(const float* __restrict__ qpw, const float* __restrict__ qpb,
            const float* __restrict__ kpw, const float* __restrict__ kpb,
            const float* __restrict__ vpw, const float* __restrict__ vpb)
{
    __shared__ __align__(16) __half As[2][128 * 40];
    __shared__ __align__(16) __half Bs[2][32 * 136];

    int mt = blockIdx.x, nt = blockIdx.y, tb = blockIdx.z;
    int t = tb >> 3, b = tb & 7;
    const float* W    = (t == 0) ? qpw : (t == 1) ? kpw : vpw;
    const float* bias = (t == 0) ? qpb : (t == 1) ? kpb : vpb;
    const __half* Yt = g_y  + (size_t)t * IMG + (size_t)b * CHWn;
    __half*       Cm = g_qkv + (size_t)t * IMG + (size_t)b * CHWn;
    int m0 = mt * 128, n0 = nt * 128;

    int tid = threadIdx.x, lane = tid & 31, warp = tid >> 5;
    int wm = warp >> 2, wn = warp & 3, g = lane >> 2, tg = lane & 3;

    int rA = tid >> 1, cA = (tid & 1) * 16;   // A: 128 rows x 32 cols
    int rB = tid >> 3, cB = (tid & 7) * 16;   // B: 32 rows x 128 cols

    float acc[4][4][4];
    #pragma unroll
    for (int i = 0; i < 4; i++)
        #pragma unroll
        for (int j = 0; j < 4; j++)
            #pragma unroll
            for (int r = 0; r < 4; r++) acc[i][j][r] = 0.f;

    float4 wa[4];
    uint4  yb[2];

    auto loadregs = [&](int k0) {
        const float* src = W + (size_t)(m0 + rA) * Cn + k0 + cA;
        wa[0] = *(const float4*)(src);
        wa[1] = *(const float4*)(src + 4);
        wa[2] = *(const float4*)(src + 8);
        wa[3] = *(const float4*)(src + 12);
        const uint4* ys = (const uint4*)(Yt + (size_t)(k0 + rB) * HWn + n0 + cB);
        yb[0] = ys[0];
        yb[1] = ys[1];
    };
    auto storeregs = [&](int bf) {
        uint4 u0, u1;
        u0.x = f2h2(wa[0].x, wa[0].y); u0.y = f2h2(wa[0].z, wa[0].w);
        u0.z = f2h2(wa[1].x, wa[1].y); u0.w = f2h2(wa[1].z, wa[1].w);
        u1.x = f2h2(wa[2].x, wa[2].y); u1.y = f2h2(wa[2].z, wa[2].w);
        u1.z = f2h2(wa[3].x, wa[3].y); u1.w = f2h2(wa[3].z, wa[3].w);
        *(uint4*)&As[bf][rA * 40 + cA]     = u0;
        *(uint4*)&As[bf][rA * 40 + cA + 8] = u1;
        *(uint4*)&Bs[bf][rB * 136 + cB]     = yb[0];
        *(uint4*)&Bs[bf][rB * 136 + cB + 8] = yb[1];
    };

    loadregs(0);
    storeregs(0);
    __syncthreads();

    for (int kc = 0; kc < 8; kc++) {
        int cur = kc & 1;
        if (kc < 7) loadregs((kc + 1) * 32);

        #pragma unroll
        for (int kk = 0; kk < 32; kk += 16) {
            uint32_t af[4][4], bfm[4][2];
            #pragma unroll
            for (int mi = 0; mi < 4; mi++) {
                int m = wm * 64 + mi * 16;
                af[mi][0] = *(const uint32_t*)&As[cur][(m + g    ) * 40 + kk     + 2 * tg];
                af[mi][1] = *(const uint32_t*)&As[cur][(m + g + 8) * 40 + kk     + 2 * tg];
                af[mi][2] = *(const uint32_t*)&As[cur][(m + g    ) * 40 + kk + 8 + 2 * tg];
                af[mi][3] = *(const uint32_t*)&As[cur][(m + g + 8) * 40 + kk + 8 + 2 * tg];
            }
            #pragma unroll
            for (int nh = 0; nh < 2; nh++) {
                int lrow = kk + (lane & 15);
                int lcol = wn * 32 + nh * 16 + (lane >> 4) * 8;
                ldsm4t(bfm[2 * nh][0], bfm[2 * nh][1], bfm[2 * nh + 1][0], bfm[2 * nh + 1][1],
                       smem_u32(&Bs[cur][lrow * 136 + lcol]));
            }
            #pragma unroll
            for (int mi = 0; mi < 4; mi++)
                #pragma unroll
                for (int nb = 0; nb < 4; nb++)
                    mma16(acc[mi][nb], af[mi], bfm[nb]);
        }

        if (kc < 7) {
            __syncthreads();
            storeregs(cur ^ 1);
            __syncthreads();
        }
    }

    // epilogue: +bias, half2 store g_qkv[o][s]
    #pragma unroll
    for (int mi = 0; mi < 4; mi++) {
        int m = m0 + wm * 64 + mi * 16 + g;
        float b0v = bias[m], b1v = bias[m + 8];
        #pragma unroll
        for (int nb = 0; nb < 4; nb++) {
            int n = n0 + wn * 32 + nb * 8 + tg * 2;
            *(__half2*)(Cm + (size_t)m * HWn + n) =
                __floats2half2_rn(acc[mi][nb][0] + b0v, acc[mi][nb][1] + b0v);
            *(__half2*)(Cm + (size_t)(m + 8) * HWn + n) =
                __floats2half2_rn(acc[mi][nb][2] + b1v, acc[mi][nb][3] + b1v);
        }
    }
}

// ---------------------------------------------------------------------------
// Kernel 3: per-(b,h) channel attention, fp16 mma.
//   S = Q K^T * scale (fp32 accum/smem), P = softmax (fp32, stored half
//   in-place), O = P V (fp32 accum, fp32 out)
// CTA = 1 (b,h), 512 threads, 2 q-tiles of 128 rows.
// smem: Ss fp32 128x264 | Qs half 128x24 | Ks half 256x24 (Vs 16x136 aliases Qs)
// ---------------------------------------------------------------------------
constexpr int ATTN_SMEM_BYTES = 128 * 264 * 4 + (128 * 24 + 256 * 24) * 2;  // 153600

__global__ void __launch_bounds__(512)
k_attn(float* __restrict__ out)
{
    extern __shared__ __align__(16) char smraw[];
    float*  Ss = (float*)smraw;                          // 128 x 264 fp32
    __half* Qs = (__half*)(smraw + 128 * 264 * 4);       // 128 x 24
    __half* Ks = Qs + 128 * 24;                          // 256 x 24
    __half* Vs = Qs;                                     // 16 x 136 (alias)

    int bh = blockIdx.x;
    int b = bh >> 7, h = bh & 127;
    const __half* Qg = g_qkv + (size_t)b * CHWn + (size_t)h * Wn;  // [c][w] slice
    const __half* Kg = Qg + IMG;
    const __half* Vg = Qg + 2 * IMG;
    float* Og = out + (size_t)b * CHWn + (size_t)h * Wn;

    int tid = threadIdx.x;
    int lane = tid & 31, warp = tid >> 5;
    int g = lane >> 2, tg = lane & 3;
    int wm = warp >> 2, wn = warp & 3;       // 4M x 4N warps
    const float scale = 0.17677669529663687f;  // 1/sqrt(32)

    int rQ = tid >> 2, cQ = (tid & 3) * 4;   // Q tile 128 x 16
    int rK = tid >> 1, cK = (tid & 1) * 8;   // K tile 256 x 16
    int rV = tid >> 5, cV = (tid & 31) * 4;  // V tile 16 x 128

    for (int qt = 0; qt < 2; qt++) {
        int c0 = qt * 128;

        // ---- GEMM1: S[128,256] = Q[128,128] @ K^T, warp tile 32x64 ----
        float acc1[2][8][4];
        #pragma unroll
        for (int i = 0; i < 2; i++)
            #pragma unroll
            for (int j = 0; j < 8; j++)
                #pragma unroll
                for (int r = 0; r < 4; r++) acc1[i][j][r] = 0.f;

        for (int kc = 0; kc < 8; kc++) {
            int k0 = kc * 16;
            __syncthreads();
            *(uint2*)&Qs[rQ * 24 + cQ] =
                *(const uint2*)(Qg + (size_t)(c0 + rQ) * HWn + k0 + cQ);
            *(uint4*)&Ks[rK * 24 + cK] =
                *(const uint4*)(Kg + (size_t)rK * HWn + k0 + cK);
            __syncthreads();

            uint32_t af[2][4], bf[8][2];
            #pragma unroll
            for (int mi = 0; mi < 2; mi++) {
                int m = wm * 32 + mi * 16;
                af[mi][0] = *(const uint32_t*)&Qs[(m + g    ) * 24 +     2 * tg];
                af[mi][1] = *(const uint32_t*)&Qs[(m + g + 8) * 24 +     2 * tg];
                af[mi][2] = *(const uint32_t*)&Qs[(m + g    ) * 24 + 8 + 2 * tg];
                af[mi][3] = *(const uint32_t*)&Qs[(m + g + 8) * 24 + 8 + 2 * tg];
            }
            #pragma unroll
            for (int nb = 0; nb < 8; nb++) {
                int n = wn * 64 + nb * 8;
                bf[nb][0] = *(const uint32_t*)&Ks[(n + g) * 24 +     2 * tg];
                bf[nb][1] = *(const uint32_t*)&Ks[(n + g) * 24 + 8 + 2 * tg];
            }
            #pragma unroll
            for (int mi = 0; mi < 2; mi++)
                #pragma unroll
                for (int nb = 0; nb < 8; nb++)
                    mma16(acc1[mi][nb], af[mi], bf[nb]);
        }

        // scale + write S (fp32) to smem
        #pragma unroll
        for (int mi = 0; mi < 2; mi++) {
            int m = wm * 32 + mi * 16 + g;
            #pragma unroll
            for (int nb = 0; nb < 8; nb++) {
                int n = wn * 64 + nb * 8 + tg * 2;
                *(float2*)&Ss[m * 264 + n] =
                    make_float2(acc1[mi][nb][0] * scale, acc1[mi][nb][1] * scale);
                *(float2*)&Ss[(m + 8) * 264 + n] =
                    make_float2(acc1[mi][nb][2] * scale, acc1[mi][nb][3] * scale);
            }
        }
        __syncthreads();

        // ---- softmax (fp32), write P in-place as half (row base unchanged) ----
        #pragma unroll 1
        for (int rr = 0; rr < 8; rr++) {
            int r = warp * 8 + rr;
            float v[8];
            float mx = -1e30f;
            #pragma unroll
            for (int i = 0; i < 8; i++) {
                v[i] = Ss[r * 264 + lane + 32 * i];
                mx = fmaxf(mx, v[i]);
            }
            #pragma unroll
            for (int o = 16; o > 0; o >>= 1)
                mx = fmaxf(mx, __shfl_xor_sync(0xffffffffu, mx, o));
            float s = 0.f;
            #pragma unroll
            for (int i = 0; i < 8; i++) { v[i] = __expf(v[i] - mx); s += v[i]; }
            #pragma unroll
            for (int o = 16; o > 0; o >>= 1)
                s += __shfl_xor_sync(0xffffffffu, s, o);
            float inv = 1.f / s;
            __half* Pr = (__half*)(Ss + (size_t)r * 264);
            #pragma unroll
            for (int i = 0; i < 8; i++)
                Pr[lane + 32 * i] = __float2half_rn(v[i] * inv);
        }
        __syncthreads();

        // ---- GEMM2: O[128,128] = P[128,256] @ V[256,128], warp tile 32x32 ----
        const __half* Ps = (const __half*)Ss;   // pitch 528 halves
        float acc2[2][4][4];
        #pragma unroll
        for (int i = 0; i < 2; i++)
            #pragma unroll
            for (int j = 0; j < 4; j++)
                #pragma unroll
                for (int r = 0; r < 4; r++) acc2[i][j][r] = 0.f;

        for (int kc = 0; kc < 16; kc++) {
            int k0 = kc * 16;
            __syncthreads();
            *(uint2*)&Vs[rV * 136 + cV] =
                *(const uint2*)(Vg + (size_t)(k0 + rV) * HWn + cV);
            __syncthreads();

            uint32_t af[2][4], bf[4][2];
            #pragma unroll
            for (int mi = 0; mi < 2; mi++) {
                int m = wm * 32 + mi * 16;
                af[mi][0] = *(const uint32_t*)&Ps[(size_t)(m + g    ) * 528 + k0     + 2 * tg];
                af[mi][1] = *(const uint32_t*)&Ps[(size_t)(m + g + 8) * 528 + k0     + 2 * tg];
                af[mi][2] = *(const uint32_t*)&Ps[(size_t)(m + g    ) * 528 + k0 + 8 + 2 * tg];
                af[mi][3] = *(const uint32_t*)&Ps[(size_t)(m + g + 8) * 528 + k0 + 8 + 2 * tg];
            }
            #pragma unroll
            for (int nh = 0; nh < 2; nh++) {
                int lrow = lane & 15;
                int lcol = wn * 32 + nh * 16 + (lane >> 4) * 8;
                ldsm4t(bf[2 * nh][0], bf[2 * nh][1], bf[2 * nh + 1][0], bf[2 * nh + 1][1],
                       smem_u32(&Vs[lrow * 136 + lcol]));
            }
            #pragma unroll
            for (int mi = 0; mi < 2; mi++)
                #pragma unroll
                for (int nb = 0; nb < 4; nb++)
                    mma16(acc2[mi][nb], af[mi], bf[nb]);
        }

        // epilogue: fp32 store out[b, c, h, w]
        #pragma unroll
        for (int mi = 0; mi < 2; mi++) {
            int m = wm * 32 + mi * 16 + g;
            #pragma unroll
            for (int nb = 0; nb < 4; nb++) {
                int n = wn * 32 + nb * 8 + tg * 2;
                *(float2*)(Og + (size_t)(c0 + m) * HWn + n) =
                    make_float2(acc2[mi][nb][0], acc2[mi][nb][1]);
                *(float2*)(Og + (size_t)(c0 + m + 8) * HWn + n) =
                    make_float2(acc2[mi][nb][2], acc2[mi][nb][3]);
            }
        }
    }
}

// ---------------------------------------------------------------------------
extern "C" void kernel_launch(void* const* d_in, const int* in_sizes, int n_in,
                              void* d_out, int out_size)
{
    (void)in_sizes; (void)n_in; (void)out_size;
    const float* hidden = (const float*)d_in[0];
    const float* ctx    = (const float*)d_in[1];
    const float* qdw = (const float*)d_in[2];
    const float* qdb = (const float*)d_in[3];
    const float* qpw = (const float*)d_in[4];
    const float* qpb = (const float*)d_in[5];
    const float* kdw = (const float*)d_in[6];
    const float* kdb = (const float*)d_in[7];
    const float* kpw = (const float*)d_in[8];
    const float* kpb = (const float*)d_in[9];
    const float* vdw = (const float*)d_in[10];
    const float* vdb = (const float*)d_in[11];
    const float* vpw = (const float*)d_in[12];
    const float* vpb = (const float*)d_in[13];
    float* out = (float*)d_out;

    k_dwconv<<<dim3(Hn / 16, Bn * Cn), 256>>>(hidden, ctx, qdw, qdb, kdw, kdb, vdw, vdb);
    k_pointwise<<<dim3(2, HWn / 128, 24), 256>>>(qpw, qpb, kpw, kpb, vpw, vpb);
    cudaFuncSetAttribute(k_attn, cudaFuncAttributeMaxDynamicSharedMemorySize, ATTN_SMEM_BYTES);
    k_attn<<<Bn * Hn, 512, ATTN_SMEM_BYTES>>>(out);
}

// round 10
// speedup vs baseline: 1.9968x; 1.3954x over previous
#include <cuda_runtime.h>
#include <cuda_fp16.h>
#include <cstdint>
#include <cstddef>

// ---------------------------------------------------------------------------
// CrossAttention_41497974014052  (sm_103a, legacy mma path)
// K0: W fp32 -> half pre-convert
// K1: depthwise3x3 (smem-tiled, half2 stores)
// K2: pointwise GEMM, fp16 m16n8k16, cp.async 3-stage pipeline
// K3: per-(b,h) channel attention: K/V resident smem, Q gmem-reg frags,
//     register softmax, zero-sync GEMMs
// ---------------------------------------------------------------------------

constexpr int Bn = 8, Cn = 256, Hn = 128, Wn = 128;
constexpr int HWn = Hn * Wn;                    // 16384
constexpr size_t CHWn = (size_t)Cn * HWn;       // 4194304
constexpr size_t IMG  = (size_t)Bn * CHWn;      // 33554432

__device__ __half g_y[3 * IMG];
__device__ __half g_qkv[3 * IMG];
__device__ __half g_wh[3 * 65536];

__device__ __forceinline__ uint32_t f2h2(float a, float b) {
    __half2 h = __floats2half2_rn(a, b);
    return *reinterpret_cast<uint32_t*>(&h);
}
__device__ __forceinline__ uint32_t smem_u32(const void* p) {
    uint32_t a;
    asm("{ .reg .u64 t; cvta.to.shared.u64 t, %1; cvt.u32.u64 %0, t; }" : "=r"(a) : "l"(p));
    return a;
}
__device__ __forceinline__ void mma16(float d[4], const uint32_t a[4], const uint32_t b[2]) {
    asm volatile(
        "mma.sync.aligned.m16n8k16.row.col.f32.f16.f16.f32 "
        "{%0,%1,%2,%3}, {%4,%5,%6,%7}, {%8,%9}, {%0,%1,%2,%3};\n"
        : "+f"(d[0]), "+f"(d[1]), "+f"(d[2]), "+f"(d[3])
        : "r"(a[0]), "r"(a[1]), "r"(a[2]), "r"(a[3]), "r"(b[0]), "r"(b[1]));
}
__device__ __forceinline__ void ldsm4t(uint32_t& r0, uint32_t& r1, uint32_t& r2, uint32_t& r3,
                                       uint32_t addr) {
    asm volatile("ldmatrix.sync.aligned.m8n8.x4.trans.shared.b16 {%0,%1,%2,%3}, [%4];"
                 : "=r"(r0), "=r"(r1), "=r"(r2), "=r"(r3) : "r"(addr));
}
__device__ __forceinline__ void cp16(uint32_t dst, const void* src) {
    asm volatile("cp.async.cg.shared.global [%0], [%1], 16;"
                 :: "r"(dst), "l"((size_t)__cvta_generic_to_global(src)) : "memory");
}
#define CP_COMMIT() asm volatile("cp.async.commit_group;" ::: "memory")
#define CP_WAIT1()  asm volatile("cp.async.wait_group 1;" ::: "memory")
#define CP_WAIT0()  asm volatile("cp.async.wait_group 0;" ::: "memory")

// ---------------------------------------------------------------------------
// Kernel 0: W fp32 -> half. grid (128, 3), 256 thr.
// ---------------------------------------------------------------------------
__global__ void k_wconv(const float* __restrict__ qpw, const float* __restrict__ kpw,
                        const float* __restrict__ vpw)
{
    int t = blockIdx.y;
    const float* W = (t == 0) ? qpw : (t == 1) ? kpw : vpw;
    int i = (blockIdx.x * 256 + threadIdx.x) * 2;
    float2 v = *(const float2*)(W + i);
    *(__half2*)(g_wh + t * 65536 + i) = __floats2half2_rn(v.x, v.y);
}

// ---------------------------------------------------------------------------
// Kernel 1: depthwise 3x3 (SAME) + bias, smem-tiled, 2 cols/thread (half2 out)
// grid (H/16, B*C), 256 threads.
// ---------------------------------------------------------------------------
__global__ void __launch_bounds__(256)
k_dwconv(const float* __restrict__ hidden, const float* __restrict__ ctx,
         const float* __restrict__ qw, const float* __restrict__ qb,
         const float* __restrict__ kw, const float* __restrict__ kb,
         const float* __restrict__ vw, const float* __restrict__ vb)
{
    __shared__ float shH[18][132];
    __shared__ float shC[18][132];

    int h0 = blockIdx.x * 16;
    int bc = blockIdx.y;
    int c  = bc & (Cn - 1);
    int tid = threadIdx.x;
    size_t base = (size_t)bc * HWn;
    const float* xh = hidden + base;
    const float* xc = ctx + base;

    for (int idx = tid; idx < 18 * 130; idx += 256) {
        int r = idx / 130, ci = idx - r * 130;
        int hh = h0 + r - 1, ww = ci - 1;
        bool ok = ((unsigned)hh < (unsigned)Hn) & ((unsigned)ww < (unsigned)Wn);
        float vh = 0.f, vc = 0.f;
        if (ok) { int o = hh * Wn + ww; vh = xh[o]; vc = xc[o]; }
        shH[r][ci] = vh;
        shC[r][ci] = vc;
    }

    float wq[9], wk[9], wv[9];
    #pragma unroll
    for (int i = 0; i < 9; i++) {
        wq[i] = qw[c * 9 + i]; wk[i] = kw[c * 9 + i]; wv[i] = vw[c * 9 + i];
    }
    float bq = qb[c], bk = kb[c], bv = vb[c];
    __syncthreads();

    int w2 = (tid & 63) * 2;
    int rb = (tid >> 6) * 4;

    float A0[4], A1[4], A2[4], B0[4], B1[4], B2[4];
    #pragma unroll
    for (int j = 0; j < 4; j++) {
        A0[j] = shH[rb][w2 + j];     A1[j] = shH[rb + 1][w2 + j];
        B0[j] = shC[rb][w2 + j];     B1[j] = shC[rb + 1][w2 + j];
    }

    #pragma unroll
    for (int rr = 0; rr < 4; rr++) {
        #pragma unroll
        for (int j = 0; j < 4; j++) {
            A2[j] = shH[rb + rr + 2][w2 + j];
            B2[j] = shC[rb + rr + 2][w2 + j];
        }
        float aq0 = bq, aq1 = bq, ak0 = bk, ak1 = bk, av0 = bv, av1 = bv;
        #pragma unroll
        for (int j = 0; j < 3; j++) {
            aq0 += wq[j] * A0[j]     + wq[3 + j] * A1[j]     + wq[6 + j] * A2[j];
            aq1 += wq[j] * A0[j + 1] + wq[3 + j] * A1[j + 1] + wq[6 + j] * A2[j + 1];
            ak0 += wk[j] * B0[j]     + wk[3 + j] * B1[j]     + wk[6 + j] * B2[j];
            ak1 += wk[j] * B0[j + 1] + wk[3 + j] * B1[j + 1] + wk[6 + j] * B2[j + 1];
            av0 += wv[j] * B0[j]     + wv[3 + j] * B1[j]     + wv[6 + j] * B2[j];
            av1 += wv[j] * B0[j + 1] + wv[3 + j] * B1[j + 1] + wv[6 + j] * B2[j + 1];
        }
        size_t o = base + (size_t)(h0 + rb + rr) * Wn + w2;
        *(__half2*)(g_y + o)           = __floats2half2_rn(aq0, aq1);
        *(__half2*)(g_y + IMG + o)     = __floats2half2_rn(ak0, ak1);
        *(__half2*)(g_y + 2 * IMG + o) = __floats2half2_rn(av0, av1);
        #pragma unroll
        for (int j = 0; j < 4; j++) {
            A0[j] = A1[j]; A1[j] = A2[j];
            B0[j] = B1[j]; B1[j] = B2[j];
        }
    }
}

// ---------------------------------------------------------------------------
// Kernel 2: pointwise GEMM  D[o][s] = sum_c W[o][c] * y[c][s] + bias[o]
// fp16 m16n8k16, CTA 128x128, K=256 in 8 chunks of 32, cp.async 3-stage.
// 256 thr = 8 warps (2M x 4N), warp tile 64x32.
// smem/stage: As 128x40 half (10240B), Bs 32x136 half (8704B); 3 stages.
// grid (2, 128, 24)
// ---------------------------------------------------------------------------
constexpr int PW_AS_STRIDE = 128 * 40 * 2;   // 10240
constexpr int PW_BS_BASE   = 3 * PW_AS_STRIDE;
constexpr int PW_BS_STRIDE = 32 * 136 * 2;   // 8704
constexpr int PW_SMEM      = PW_BS_BASE + 3 * PW_BS_STRIDE;  // 56832

__global__ void __launch_bounds__(256)
k_pointwise(const float* __restrict__ qpb, const float* __restrict__ kpb,
            const float* __restrict__ vpb)
{
    extern __shared__ __align__(16) char dyn[];
    uint32_t sb = smem_u32(dyn);

    int mt = blockIdx.x, nt = blockIdx.y, tb = blockIdx.z;
    int t = tb >> 3, b = tb & 7;
    const float* bias = (t == 0) ? qpb : (t == 1) ? kpb : vpb;
    const __half* Wh = g_wh + t * 65536;
    const __half* Yt = g_y  + (size_t)t * IMG + (size_t)b * CHWn;
    __half*       Cm = g_qkv + (size_t)t * IMG + (size_t)b * CHWn;
    int m0 = mt * 128, n0 = nt * 128;

    int tid = threadIdx.x, lane = tid & 31, warp = tid >> 5;
    int wm = warp >> 2, wn = warp & 3, g = lane >> 2, tg = lane & 3;

    int rA = tid >> 1, cA = (tid & 1) * 16;   // A: 128 x 32
    int rB = tid >> 3, cB = (tid & 7) * 16;   // B: 32 x 128

    auto issue = [&](int stage) {
        int buf = stage % 3;
        int k0 = stage * 32;
        uint32_t asb = sb + buf * PW_AS_STRIDE;
        uint32_t bsb = sb + PW_BS_BASE + buf * PW_BS_STRIDE;
        const __half* srcA = Wh + (size_t)(m0 + rA) * Cn + k0 + cA;
        cp16(asb + (rA * 40 + cA) * 2, srcA);
        cp16(asb + (rA * 40 + cA + 8) * 2, srcA + 8);
        const __half* srcB = Yt + (size_t)(k0 + rB) * HWn + n0 + cB;
        cp16(bsb + (rB * 136 + cB) * 2, srcB);
        cp16(bsb + (rB * 136 + cB + 8) * 2, srcB + 8);
        CP_COMMIT();
    };

    float acc[4][4][4];
    #pragma unroll
    for (int i = 0; i < 4; i++)
        #pragma unroll
        for (int j = 0; j < 4; j++)
            #pragma unroll
            for (int r = 0; r < 4; r++) acc[i][j][r] = 0.f;

    issue(0);
    issue(1);

    for (int kc = 0; kc < 8; kc++) {
        if (kc < 7) { CP_WAIT1(); } else { CP_WAIT0(); }
        __syncthreads();
        if (kc + 2 < 8) issue(kc + 2);

        int buf = kc % 3;
        const __half* As = (const __half*)(dyn + buf * PW_AS_STRIDE);
        uint32_t bsb = sb + PW_BS_BASE + buf * PW_BS_STRIDE;
        const __half* Bsp = (const __half*)(dyn + PW_BS_BASE + buf * PW_BS_STRIDE);
        (void)Bsp;

        #pragma unroll
        for (int kk = 0; kk < 32; kk += 16) {
            uint32_t af[4][4], bfm[4][2];
            #pragma unroll
            for (int mi = 0; mi < 4; mi++) {
                int m = wm * 64 + mi * 16;
                af[mi][0] = *(const uint32_t*)&As[(m + g    ) * 40 + kk     + 2 * tg];
                af[mi][1] = *(const uint32_t*)&As[(m + g + 8) * 40 + kk     + 2 * tg];
                af[mi][2] = *(const uint32_t*)&As[(m + g    ) * 40 + kk + 8 + 2 * tg];
                af[mi][3] = *(const uint32_t*)&As[(m + g + 8) * 40 + kk + 8 + 2 * tg];
            }
            #pragma unroll
            for (int nh = 0; nh < 2; nh++) {
                int lrow = kk + (lane & 15);
                int lcol = wn * 32 + nh * 16 + (lane >> 4) * 8;
                ldsm4t(bfm[2 * nh][0], bfm[2 * nh][1], bfm[2 * nh + 1][0], bfm[2 * nh + 1][1],
                       bsb + (lrow * 136 + lcol) * 2);
            }
            #pragma unroll
            for (int mi = 0; mi < 4; mi++)
                #pragma unroll
                for (int nb = 0; nb < 4; nb++)
                    mma16(acc[mi][nb], af[mi], bfm[nb]);
        }
    }

    #pragma unroll
    for (int mi = 0; mi < 4; mi++) {
        int m = m0 + wm * 64 + mi * 16 + g;
        float b0v = bias[m], b1v = bias[m + 8];
        #pragma unroll
        for (int nb = 0; nb < 4; nb++) {
            int n = n0 + wn * 32 + nb * 8 + tg * 2;
            *(__half2*)(Cm + (size_t)m * HWn + n) =
                __floats2half2_rn(acc[mi][nb][0] + b0v, acc[mi][nb][1] + b0v);
            *(__half2*)(Cm + (size_t)(m + 8) * HWn + n) =
                __floats2half2_rn(acc[mi][nb][2] + b1v, acc[mi][nb][3] + b1v);
        }
    }
}

// ---------------------------------------------------------------------------
// Kernel 3: per-(b,h) channel attention.
//   K/V resident in smem (loaded once). Q A-frags direct from gmem.
//   Register softmax (quad shfl + cross-warp smem partials) -> P half in smem.
// CTA = 1 (b,h), 512 threads (16 warps, 4M x 4N), 2 q-tiles of 128 rows.
// smem: Ps 128x264 half | Ks 256x136 half | Vs 256x136 half | red 2x4x128 f32
// ---------------------------------------------------------------------------
constexpr int K3_PS   = 0;
constexpr int K3_KS   = 128 * 264 * 2;            // 67584
constexpr int K3_VS   = K3_KS + 256 * 136 * 2;    // 137216
constexpr int K3_RED  = K3_VS + 256 * 136 * 2;    // 206848
constexpr int K3_SMEM = K3_RED + 2 * 4 * 128 * 4; // 210944

__global__ void __launch_bounds__(512)
k_attn(float* __restrict__ out)
{
    extern __shared__ __align__(16) char smraw[];
    __half* Ps = (__half*)(smraw + K3_PS);    // pitch 264
    __half* Ks = (__half*)(smraw + K3_KS);    // pitch 136
    __half* Vs = (__half*)(smraw + K3_VS);    // pitch 136
    float*  redm = (float*)(smraw + K3_RED);  // [4][128]
    float*  reds = redm + 512;                // [4][128]

    int bh = blockIdx.x;
    int b = bh >> 7, h = bh & 127;
    const __half* Qg = g_qkv + (size_t)b * CHWn + (size_t)h * Wn;  // [c][w]
    const __half* Kg = Qg + IMG;
    const __half* Vg = Qg + 2 * IMG;
    float* Og = out + (size_t)b * CHWn + (size_t)h * Wn;

    int tid = threadIdx.x;
    int lane = tid & 31, warp = tid >> 5;
    int g = lane >> 2, tg = lane & 3;
    int wm = warp >> 2, wn = warp & 3;
    const float scale = 0.17677669529663687f;  // 1/sqrt(32)

    // ---- prologue: load K and V fully into smem (coalesced 16B) ----
    #pragma unroll
    for (int i = 0; i < 8; i++) {
        int chunk = tid + i * 512;            // 0..4095
        int row = chunk >> 4, col = (chunk & 15) * 8;
        *(uint4*)&Ks[row * 136 + col] = *(const uint4*)(Kg + (size_t)row * HWn + col);
        *(uint4*)&Vs[row * 136 + col] = *(const uint4*)(Vg + (size_t)row * HWn + col);
    }
    __syncthreads();

    for (int qt = 0; qt < 2; qt++) {
        int c0 = qt * 128;

        // ---- GEMM1: S[128,256] = Q @ K^T, K resident, Q frags from gmem ----
        float acc1[2][8][4];
        #pragma unroll
        for (int i = 0; i < 2; i++)
            #pragma unroll
            for (int j = 0; j < 8; j++)
                #pragma unroll
                for (int r = 0; r < 4; r++) acc1[i][j][r] = 0.f;

        uint32_t afb[2][2][4];
        {
            #pragma unroll
            for (int mi = 0; mi < 2; mi++) {
                const __half* q0 = Qg + (size_t)(c0 + wm * 32 + mi * 16 + g) * HWn + 2 * tg;
                afb[0][mi][0] = *(const uint32_t*)(q0);
                afb[0][mi][1] = *(const uint32_t*)(q0 + 8 * HWn);
                afb[0][mi][2] = *(const uint32_t*)(q0 + 8);
                afb[0][mi][3] = *(const uint32_t*)(q0 + 8 * HWn + 8);
            }
        }
        #pragma unroll
        for (int kc = 0; kc < 8; kc++) {
            int cur = kc & 1;
            if (kc < 7) {
                int k0 = (kc + 1) * 16;
                #pragma unroll
                for (int mi = 0; mi < 2; mi++) {
                    const __half* q0 = Qg + (size_t)(c0 + wm * 32 + mi * 16 + g) * HWn + k0 + 2 * tg;
                    afb[cur ^ 1][mi][0] = *(const uint32_t*)(q0);
                    afb[cur ^ 1][mi][1] = *(const uint32_t*)(q0 + 8 * HWn);
                    afb[cur ^ 1][mi][2] = *(const uint32_t*)(q0 + 8);
                    afb[cur ^ 1][mi][3] = *(const uint32_t*)(q0 + 8 * HWn + 8);
                }
            }
            int k0 = kc * 16;
            uint32_t bf[8][2];
            #pragma unroll
            for (int nb = 0; nb < 8; nb++) {
                int n = wn * 64 + nb * 8;
                bf[nb][0] = *(const uint32_t*)&Ks[(n + g) * 136 + k0     + 2 * tg];
                bf[nb][1] = *(const uint32_t*)&Ks[(n + g) * 136 + k0 + 8 + 2 * tg];
            }
            #pragma unroll
            for (int mi = 0; mi < 2; mi++)
                #pragma unroll
                for (int nb = 0; nb < 8; nb++)
                    mma16(acc1[mi][nb], afb[cur][mi], bf[nb]);
        }

        // scale
        #pragma unroll
        for (int mi = 0; mi < 2; mi++)
            #pragma unroll
            for (int nb = 0; nb < 8; nb++)
                #pragma unroll
                for (int r = 0; r < 4; r++) acc1[mi][nb][r] *= scale;

        // ---- register softmax over 256 cols ----
        // thread's rows: i=0..3 -> r_i = wm*32 + (i>>1)*16 + (i&1)*8 + g
        float mx[4] = {-1e30f, -1e30f, -1e30f, -1e30f};
        #pragma unroll
        for (int mi = 0; mi < 2; mi++)
            #pragma unroll
            for (int nb = 0; nb < 8; nb++) {
                mx[2 * mi]     = fmaxf(mx[2 * mi],     fmaxf(acc1[mi][nb][0], acc1[mi][nb][1]));
                mx[2 * mi + 1] = fmaxf(mx[2 * mi + 1], fmaxf(acc1[mi][nb][2], acc1[mi][nb][3]));
            }
        #pragma unroll
        for (int o = 1; o <= 2; o <<= 1)
            #pragma unroll
            for (int i = 0; i < 4; i++)
                mx[i] = fmaxf(mx[i], __shfl_xor_sync(0xffffffffu, mx[i], o));
        if (tg == 0) {
            #pragma unroll
            for (int i = 0; i < 4; i++) {
                int r = wm * 32 + (i >> 1) * 16 + (i & 1) * 8 + g;
                redm[wn * 128 + r] = mx[i];
            }
        }
        __syncthreads();
        float fm[4];
        #pragma unroll
        for (int i = 0; i < 4; i++) {
            int r = wm * 32 + (i >> 1) * 16 + (i & 1) * 8 + g;
            fm[i] = fmaxf(fmaxf(redm[r], redm[128 + r]), fmaxf(redm[256 + r], redm[384 + r]));
        }
        float sum[4] = {0.f, 0.f, 0.f, 0.f};
        #pragma unroll
        for (int mi = 0; mi < 2; mi++)
            #pragma unroll
            for (int nb = 0; nb < 8; nb++) {
                acc1[mi][nb][0] = __expf(acc1[mi][nb][0] - fm[2 * mi]);
                acc1[mi][nb][1] = __expf(acc1[mi][nb][1] - fm[2 * mi]);
                acc1[mi][nb][2] = __expf(acc1[mi][nb][2] - fm[2 * mi + 1]);
                acc1[mi][nb][3] = __expf(acc1[mi][nb][3] - fm[2 * mi + 1]);
                sum[2 * mi]     += acc1[mi][nb][0] + acc1[mi][nb][1];
                sum[2 * mi + 1] += acc1[mi][nb][2] + acc1[mi][nb][3];
            }
        #pragma unroll
        for (int o = 1; o <= 2; o <<= 1)
            #pragma unroll
            for (int i = 0; i < 4; i++)
                sum[i] += __shfl_xor_sync(0xffffffffu, sum[i], o);
        if (tg == 0) {
            #pragma unroll
            for (int i = 0; i < 4; i++) {
                int r = wm * 32 + (i >> 1) * 16 + (i & 1) * 8 + g;
                reds[wn * 128 + r] = sum[i];
            }
        }
        __syncthreads();
        float inv[4];
        #pragma unroll
        for (int i = 0; i < 4; i++) {
            int r = wm * 32 + (i >> 1) * 16 + (i & 1) * 8 + g;
            inv[i] = 1.f / (reds[r] + reds[128 + r] + reds[256 + r] + reds[384 + r]);
        }
        // write P (half) to Ps
        #pragma unroll
        for (int mi = 0; mi < 2; mi++) {
            int r0 = wm * 32 + mi * 16 + g;
            #pragma unroll
            for (int nb = 0; nb < 8; nb++) {
                int col = wn * 64 + nb * 8 + 2 * tg;
                *(uint32_t*)&Ps[r0 * 264 + col] =
                    f2h2(acc1[mi][nb][0] * inv[2 * mi], acc1[mi][nb][1] * inv[2 * mi]);
                *(uint32_t*)&Ps[(r0 + 8) * 264 + col] =
                    f2h2(acc1[mi][nb][2] * inv[2 * mi + 1], acc1[mi][nb][3] * inv[2 * mi + 1]);
            }
        }
        __syncthreads();

        // ---- GEMM2: O[128,128] = P @ V, both resident, no syncs ----
        float acc2[2][4][4];
        #pragma unroll
        for (int i = 0; i < 2; i++)
            #pragma unroll
            for (int j = 0; j < 4; j++)
                #pragma unroll
                for (int r = 0; r < 4; r++) acc2[i][j][r] = 0.f;

        #pragma unroll 4
        for (int kc = 0; kc < 16; kc++) {
            int k0 = kc * 16;
            uint32_t af[2][4], bf[4][2];
            #pragma unroll
            for (int mi = 0; mi < 2; mi++) {
                int m = wm * 32 + mi * 16;
                af[mi][0] = *(const uint32_t*)&Ps[(m + g    ) * 264 + k0     + 2 * tg];
                af[mi][1] = *(const uint32_t*)&Ps[(m + g + 8) * 264 + k0     + 2 * tg];
                af[mi][2] = *(const uint32_t*)&Ps[(m + g    ) * 264 + k0 + 8 + 2 * tg];
                af[mi][3] = *(const uint32_t*)&Ps[(m + g + 8) * 264 + k0 + 8 + 2 * tg];
            }
            #pragma unroll
            for (int nh = 0; nh < 2; nh++) {
                int lrow = k0 + (lane & 15);
                int lcol = wn * 32 + nh * 16 + (lane >> 4) * 8;
                ldsm4t(bf[2 * nh][0], bf[2 * nh][1], bf[2 * nh + 1][0], bf[2 * nh + 1][1],
                       smem_u32(&Vs[lrow * 136 + lcol]));
            }
            #pragma unroll
            for (int mi = 0; mi < 2; mi++)
                #pragma unroll
                for (int nb = 0; nb < 4; nb++)
                    mma16(acc2[mi][nb], af[mi], bf[nb]);
        }

        // epilogue: fp32 store out[b, c, h, w]
        #pragma unroll
        for (int mi = 0; mi < 2; mi++) {
            int m = wm * 32 + mi * 16 + g;
            #pragma unroll
            for (int nb = 0; nb < 4; nb++) {
                int n = wn * 32 + nb * 8 + tg * 2;
                *(float2*)(Og + (size_t)(c0 + m) * HWn + n) =
                    make_float2(acc2[mi][nb][0], acc2[mi][nb][1]);
                *(float2*)(Og + (size_t)(c0 + m + 8) * HWn + n) =
                    make_float2(acc2[mi][nb][2], acc2[mi][nb][3]);
            }
        }
    }
}

// ---------------------------------------------------------------------------
extern "C" void kernel_launch(void* const* d_in, const int* in_sizes, int n_in,
                              void* d_out, int out_size)
{
    (void)in_sizes; (void)n_in; (void)out_size;
    const float* hidden = (const float*)d_in[0];
    const float* ctx    = (const float*)d_in[1];
    const float* qdw = (const float*)d_in[2];
    const float* qdb = (const float*)d_in[3];
    const float* qpw = (const float*)d_in[4];
    const float* qpb = (const float*)d_in[5];
    const float* kdw = (const float*)d_in[6];
    const float* kdb = (const float*)d_in[7];
    const float* kpw = (const float*)d_in[8];
    const float* kpb = (const float*)d_in[9];
    const float* vdw = (const float*)d_in[10];
    const float* vdb = (const float*)d_in[11];
    const float* vpw = (const float*)d_in[12];
    const float* vpb = (const float*)d_in[13];
    float* out = (float*)d_out;

    k_wconv<<<dim3(128, 3), 256>>>(qpw, kpw, vpw);
    k_dwconv<<<dim3(Hn / 16, Bn * Cn), 256>>>(hidden, ctx, qdw, qdb, kdw, kdb, vdw, vdb);

    cudaFuncSetAttribute(k_pointwise, cudaFuncAttributeMaxDynamicSharedMemorySize, PW_SMEM);
    k_pointwise<<<dim3(2, HWn / 128, 24), 256, PW_SMEM>>>(qpb, kpb, vpb);

    cudaFuncSetAttribute(k_attn, cudaFuncAttributeMaxDynamicSharedMemorySize, K3_SMEM);
    k_attn<<<Bn * Hn, 512, K3_SMEM>>>(out);
}

// round 11
// speedup vs baseline: 2.3864x; 1.1951x over previous
#include <cuda_runtime.h>
#include <cuda_fp16.h>
#include <cstdint>
#include <cstddef>

// ---------------------------------------------------------------------------
// CrossAttention_41497974014052  (sm_103a, legacy mma path)
// K0: W fp32 -> half pre-convert
// K1: depthwise3x3 (smem-tiled, half2 stores)
// K2: pointwise GEMM, fp16 m16n8k16, cp.async 3-stage, ldmatrix frags
// K3: per-(b,h) channel attention: K/V/Q resident smem (cp.async),
//     all-ldmatrix frags, register softmax, zero-sync GEMM inner loops
// ---------------------------------------------------------------------------

constexpr int Bn = 8, Cn = 256, Hn = 128, Wn = 128;
constexpr int HWn = Hn * Wn;                    // 16384
constexpr size_t CHWn = (size_t)Cn * HWn;       // 4194304
constexpr size_t IMG  = (size_t)Bn * CHWn;      // 33554432

__device__ __half g_y[3 * IMG];
__device__ __half g_qkv[3 * IMG];
__device__ __half g_wh[3 * 65536];

__device__ __forceinline__ uint32_t f2h2(float a, float b) {
    __half2 h = __floats2half2_rn(a, b);
    return *reinterpret_cast<uint32_t*>(&h);
}
__device__ __forceinline__ uint32_t smem_u32(const void* p) {
    uint32_t a;
    asm("{ .reg .u64 t; cvta.to.shared.u64 t, %1; cvt.u32.u64 %0, t; }" : "=r"(a) : "l"(p));
    return a;
}
__device__ __forceinline__ void mma16(float d[4], const uint32_t a[4], const uint32_t b[2]) {
    asm volatile(
        "mma.sync.aligned.m16n8k16.row.col.f32.f16.f16.f32 "
        "{%0,%1,%2,%3}, {%4,%5,%6,%7}, {%8,%9}, {%0,%1,%2,%3};\n"
        : "+f"(d[0]), "+f"(d[1]), "+f"(d[2]), "+f"(d[3])
        : "r"(a[0]), "r"(a[1]), "r"(a[2]), "r"(a[3]), "r"(b[0]), "r"(b[1]));
}
__device__ __forceinline__ void ldsm4(uint32_t& r0, uint32_t& r1, uint32_t& r2, uint32_t& r3,
                                      uint32_t addr) {
    asm volatile("ldmatrix.sync.aligned.m8n8.x4.shared.b16 {%0,%1,%2,%3}, [%4];"
                 : "=r"(r0), "=r"(r1), "=r"(r2), "=r"(r3) : "r"(addr));
}
__device__ __forceinline__ void ldsm4t(uint32_t& r0, uint32_t& r1, uint32_t& r2, uint32_t& r3,
                                       uint32_t addr) {
    asm volatile("ldmatrix.sync.aligned.m8n8.x4.trans.shared.b16 {%0,%1,%2,%3}, [%4];"
                 : "=r"(r0), "=r"(r1), "=r"(r2), "=r"(r3) : "r"(addr));
}
__device__ __forceinline__ void cp16(uint32_t dst, const void* src) {
    asm volatile("cp.async.cg.shared.global [%0], [%1], 16;"
                 :: "r"(dst), "l"((size_t)__cvta_generic_to_global(src)) : "memory");
}
#define CP_COMMIT() asm volatile("cp.async.commit_group;" ::: "memory")
#define CP_WAIT1()  asm volatile("cp.async.wait_group 1;" ::: "memory")
#define CP_WAIT0()  asm volatile("cp.async.wait_group 0;" ::: "memory")

// ---------------------------------------------------------------------------
// Kernel 0: W fp32 -> half. grid (128, 3), 256 thr.
// ---------------------------------------------------------------------------
__global__ void k_wconv(const float* __restrict__ qpw, const float* __restrict__ kpw,
                        const float* __restrict__ vpw)
{
    int t = blockIdx.y;
    const float* W = (t == 0) ? qpw : (t == 1) ? kpw : vpw;
    int i = (blockIdx.x * 256 + threadIdx.x) * 2;
    float2 v = *(const float2*)(W + i);
    *(__half2*)(g_wh + t * 65536 + i) = __floats2half2_rn(v.x, v.y);
}

// ---------------------------------------------------------------------------
// Kernel 1: depthwise 3x3 (SAME) + bias, smem-tiled, 2 cols/thread (half2 out)
// grid (H/16, B*C), 256 threads.
// ---------------------------------------------------------------------------
__global__ void __launch_bounds__(256)
k_dwconv(const float* __restrict__ hidden, const float* __restrict__ ctx,
         const float* __restrict__ qw, const float* __restrict__ qb,
         const float* __restrict__ kw, const float* __restrict__ kb,
         const float* __restrict__ vw, const float* __restrict__ vb)
{
    __shared__ float shH[18][132];
    __shared__ float shC[18][132];

    int h0 = blockIdx.x * 16;
    int bc = blockIdx.y;
    int c  = bc & (Cn - 1);
    int tid = threadIdx.x;
    size_t base = (size_t)bc * HWn;
    const float* xh = hidden + base;
    const float* xc = ctx + base;

    for (int idx = tid; idx < 18 * 130; idx += 256) {
        int r = idx / 130, ci = idx - r * 130;
        int hh = h0 + r - 1, ww = ci - 1;
        bool ok = ((unsigned)hh < (unsigned)Hn) & ((unsigned)ww < (unsigned)Wn);
        float vh = 0.f, vc = 0.f;
        if (ok) { int o = hh * Wn + ww; vh = xh[o]; vc = xc[o]; }
        shH[r][ci] = vh;
        shC[r][ci] = vc;
    }

    float wq[9], wk[9], wv[9];
    #pragma unroll
    for (int i = 0; i < 9; i++) {
        wq[i] = qw[c * 9 + i]; wk[i] = kw[c * 9 + i]; wv[i] = vw[c * 9 + i];
    }
    float bq = qb[c], bk = kb[c], bv = vb[c];
    __syncthreads();

    int w2 = (tid & 63) * 2;
    int rb = (tid >> 6) * 4;

    float A0[4], A1[4], A2[4], B0[4], B1[4], B2[4];
    #pragma unroll
    for (int j = 0; j < 4; j++) {
        A0[j] = shH[rb][w2 + j];     A1[j] = shH[rb + 1][w2 + j];
        B0[j] = shC[rb][w2 + j];     B1[j] = shC[rb + 1][w2 + j];
    }

    #pragma unroll
    for (int rr = 0; rr < 4; rr++) {
        #pragma unroll
        for (int j = 0; j < 4; j++) {
            A2[j] = shH[rb + rr + 2][w2 + j];
            B2[j] = shC[rb + rr + 2][w2 + j];
        }
        float aq0 = bq, aq1 = bq, ak0 = bk, ak1 = bk, av0 = bv, av1 = bv;
        #pragma unroll
        for (int j = 0; j < 3; j++) {
            aq0 += wq[j] * A0[j]     + wq[3 + j] * A1[j]     + wq[6 + j] * A2[j];
            aq1 += wq[j] * A0[j + 1] + wq[3 + j] * A1[j + 1] + wq[6 + j] * A2[j + 1];
            ak0 += wk[j] * B0[j]     + wk[3 + j] * B1[j]     + wk[6 + j] * B2[j];
            ak1 += wk[j] * B0[j + 1] + wk[3 + j] * B1[j + 1] + wk[6 + j] * B2[j + 1];
            av0 += wv[j] * B0[j]     + wv[3 + j] * B1[j]     + wv[6 + j] * B2[j];
            av1 += wv[j] * B0[j + 1] + wv[3 + j] * B1[j + 1] + wv[6 + j] * B2[j + 1];
        }
        size_t o = base + (size_t)(h0 + rb + rr) * Wn + w2;
        *(__half2*)(g_y + o)           = __floats2half2_rn(aq0, aq1);
        *(__half2*)(g_y + IMG + o)     = __floats2half2_rn(ak0, ak1);
        *(__half2*)(g_y + 2 * IMG + o) = __floats2half2_rn(av0, av1);
        #pragma unroll
        for (int j = 0; j < 4; j++) {
            A0[j] = A1[j]; A1[j] = A2[j];
            B0[j] = B1[j]; B1[j] = B2[j];
        }
    }
}

// ---------------------------------------------------------------------------
// Kernel 2: pointwise GEMM  D[o][s] = sum_c W[o][c] * y[c][s] + bias[o]
// fp16 m16n8k16, CTA 128x128, K=256 in 8 chunks of 32, cp.async 3-stage.
// 256 thr = 8 warps (2M x 4N), warp tile 64x32, ldmatrix frags.
// grid (2, 128, 24)
// ---------------------------------------------------------------------------
constexpr int PW_AS_STRIDE = 128 * 40 * 2;   // 10240
constexpr int PW_BS_BASE   = 3 * PW_AS_STRIDE;
constexpr int PW_BS_STRIDE = 32 * 136 * 2;   // 8704
constexpr int PW_SMEM      = PW_BS_BASE + 3 * PW_BS_STRIDE;  // 56832

__global__ void __launch_bounds__(256)
k_pointwise(const float* __restrict__ qpb, const float* __restrict__ kpb,
            const float* __restrict__ vpb)
{
    extern __shared__ __align__(16) char dyn[];
    uint32_t sb = smem_u32(dyn);

    int mt = blockIdx.x, nt = blockIdx.y, tb = blockIdx.z;
    int t = tb >> 3, b = tb & 7;
    const float* bias = (t == 0) ? qpb : (t == 1) ? kpb : vpb;
    const __half* Wh = g_wh + t * 65536;
    const __half* Yt = g_y  + (size_t)t * IMG + (size_t)b * CHWn;
    __half*       Cm = g_qkv + (size_t)t * IMG + (size_t)b * CHWn;
    int m0 = mt * 128, n0 = nt * 128;

    int tid = threadIdx.x, lane = tid & 31, warp = tid >> 5;
    int wm = warp >> 2, wn = warp & 3, g = lane >> 2, tg = lane & 3;

    int rA = tid >> 1, cA = (tid & 1) * 16;   // A: 128 x 32
    int rB = tid >> 3, cB = (tid & 7) * 16;   // B: 32 x 128

    // ldmatrix lane geometry
    int aRow = wm * 64 + (lane & 15);         // + mi*16, pitch 40
    int aKoff = (lane >> 4) * 8;              // + kk

    auto issue = [&](int stage) {
        int buf = stage % 3;
        int k0 = stage * 32;
        uint32_t asb = sb + buf * PW_AS_STRIDE;
        uint32_t bsb = sb + PW_BS_BASE + buf * PW_BS_STRIDE;
        const __half* srcA = Wh + (size_t)(m0 + rA) * Cn + k0 + cA;
        cp16(asb + (rA * 40 + cA) * 2, srcA);
        cp16(asb + (rA * 40 + cA + 8) * 2, srcA + 8);
        const __half* srcB = Yt + (size_t)(k0 + rB) * HWn + n0 + cB;
        cp16(bsb + (rB * 136 + cB) * 2, srcB);
        cp16(bsb + (rB * 136 + cB + 8) * 2, srcB + 8);
        CP_COMMIT();
    };

    float acc[4][4][4];
    #pragma unroll
    for (int i = 0; i < 4; i++)
        #pragma unroll
        for (int j = 0; j < 4; j++)
            #pragma unroll
            for (int r = 0; r < 4; r++) acc[i][j][r] = 0.f;

    issue(0);
    issue(1);

    for (int kc = 0; kc < 8; kc++) {
        if (kc < 7) { CP_WAIT1(); } else { CP_WAIT0(); }
        __syncthreads();
        if (kc + 2 < 8) issue(kc + 2);

        int buf = kc % 3;
        uint32_t asb = sb + buf * PW_AS_STRIDE;
        uint32_t bsb = sb + PW_BS_BASE + buf * PW_BS_STRIDE;

        #pragma unroll
        for (int kk = 0; kk < 32; kk += 16) {
            uint32_t af[4][4], bfm[4][2];
            #pragma unroll
            for (int mi = 0; mi < 4; mi++)
                ldsm4(af[mi][0], af[mi][1], af[mi][2], af[mi][3],
                      asb + ((aRow + mi * 16) * 40 + kk + aKoff) * 2);
            #pragma unroll
            for (int nh = 0; nh < 2; nh++) {
                int lrow = kk + (lane & 15);
                int lcol = wn * 32 + nh * 16 + (lane >> 4) * 8;
                ldsm4t(bfm[2 * nh][0], bfm[2 * nh][1], bfm[2 * nh + 1][0], bfm[2 * nh + 1][1],
                       bsb + (lrow * 136 + lcol) * 2);
            }
            #pragma unroll
            for (int mi = 0; mi < 4; mi++)
                #pragma unroll
                for (int nb = 0; nb < 4; nb++)
                    mma16(acc[mi][nb], af[mi], bfm[nb]);
        }
    }

    #pragma unroll
    for (int mi = 0; mi < 4; mi++) {
        int m = m0 + wm * 64 + mi * 16 + g;
        float b0v = bias[m], b1v = bias[m + 8];
        #pragma unroll
        for (int nb = 0; nb < 4; nb++) {
            int n = n0 + wn * 32 + nb * 8 + tg * 2;
            *(__half2*)(Cm + (size_t)m * HWn + n) =
                __floats2half2_rn(acc[mi][nb][0] + b0v, acc[mi][nb][1] + b0v);
            *(__half2*)(Cm + (size_t)(m + 8) * HWn + n) =
                __floats2half2_rn(acc[mi][nb][2] + b1v, acc[mi][nb][3] + b1v);
        }
    }
}

// ---------------------------------------------------------------------------
// Kernel 3: per-(b,h) channel attention.
//   K/V resident smem; Q staged per q-tile into the Ps buffer (cp.async).
//   All frags via ldmatrix. Register softmax. Zero-sync GEMM loops.
// CTA = 1 (b,h), 512 threads (16 warps, 4M x 4N), 2 q-tiles of 128 rows.
// smem: Ps/Qs 128x264 half | Ks 256x136 | Vs 256x136 | red 2x4x128 f32
// ---------------------------------------------------------------------------
constexpr int K3_PS   = 0;
constexpr int K3_KS   = 128 * 264 * 2;            // 67584
constexpr int K3_VS   = K3_KS + 256 * 136 * 2;    // 137216
constexpr int K3_RED  = K3_VS + 256 * 136 * 2;    // 206848
constexpr int K3_SMEM = K3_RED + 2 * 4 * 128 * 4; // 210944

__global__ void __launch_bounds__(512)
k_attn(float* __restrict__ out)
{
    extern __shared__ __align__(16) char smraw[];
    __half* Ps = (__half*)(smraw + K3_PS);    // P: pitch 264 / Q: pitch 136
    float*  redm = (float*)(smraw + K3_RED);  // [4][128]
    float*  reds = redm + 512;                // [4][128]
    uint32_t sb   = smem_u32(smraw);
    uint32_t qs_b = sb + K3_PS;               // Q staging (pitch 136)
    uint32_t ps_b = sb + K3_PS;               // P (pitch 264)
    uint32_t ks_b = sb + K3_KS;
    uint32_t vs_b = sb + K3_VS;

    int bh = blockIdx.x;
    int b = bh >> 7, h = bh & 127;
    const __half* Qg = g_qkv + (size_t)b * CHWn + (size_t)h * Wn;  // [c][w]
    const __half* Kg = Qg + IMG;
    const __half* Vg = Qg + 2 * IMG;
    float* Og = out + (size_t)b * CHWn + (size_t)h * Wn;

    int tid = threadIdx.x;
    int lane = tid & 31, warp = tid >> 5;
    int g = lane >> 2, tg = lane & 3;
    int wm = warp >> 2, wn = warp & 3;
    const float scale = 0.17677669529663687f;  // 1/sqrt(32)

    // ldmatrix lane geometry (precomputed)
    int aRow  = wm * 32 + (lane & 15);        // A frags: + mi*16
    int aKoff = (lane >> 4) * 8;
    int bRowK = wn * 64 + ((lane >> 4) & 1) * 8 + (lane & 7);  // GEMM1 B: + j*16
    int bKoff = ((lane >> 3) & 1) * 8;
    int vRow  = lane & 15;                    // GEMM2 B (trans): + k0
    int vColB = wn * 32 + (lane >> 4) * 8;    // + nh*16

    auto loadQ = [&](int c0) {
        #pragma unroll
        for (int i = 0; i < 4; i++) {
            int chunk = tid + i * 512;        // 0..2047
            int row = chunk >> 4, col = (chunk & 15) * 8;
            cp16(qs_b + (row * 136 + col) * 2, Qg + (size_t)(c0 + row) * HWn + col);
        }
    };

    // ---- prologue: K, V, Q(qt=0) via cp.async ----
    #pragma unroll
    for (int i = 0; i < 8; i++) {
        int chunk = tid + i * 512;            // 0..4095
        int row = chunk >> 4, col = (chunk & 15) * 8;
        cp16(ks_b + (row * 136 + col) * 2, Kg + (size_t)row * HWn + col);
        cp16(vs_b + (row * 136 + col) * 2, Vg + (size_t)row * HWn + col);
    }
    loadQ(0);
    CP_COMMIT();
    CP_WAIT0();
    __syncthreads();

    for (int qt = 0; qt < 2; qt++) {
        int c0 = qt * 128;
        if (qt == 1) {
            __syncthreads();     // all Ps (P of qt0) reads done
            loadQ(c0);
            CP_COMMIT();
            CP_WAIT0();
            __syncthreads();
        }

        // ---- GEMM1: S[128,256] = Q @ K^T (all smem, ldmatrix) ----
        float acc1[2][8][4];
        #pragma unroll
        for (int i = 0; i < 2; i++)
            #pragma unroll
            for (int j = 0; j < 8; j++)
                #pragma unroll
                for (int r = 0; r < 4; r++) acc1[i][j][r] = 0.f;

        #pragma unroll
        for (int kc = 0; kc < 8; kc++) {
            int k0 = kc * 16;
            uint32_t af[2][4], bf[8][2];
            #pragma unroll
            for (int mi = 0; mi < 2; mi++)
                ldsm4(af[mi][0], af[mi][1], af[mi][2], af[mi][3],
                      qs_b + ((aRow + mi * 16) * 136 + k0 + aKoff) * 2);
            #pragma unroll
            for (int j = 0; j < 4; j++)
                ldsm4(bf[2 * j][0], bf[2 * j][1], bf[2 * j + 1][0], bf[2 * j + 1][1],
                      ks_b + ((bRowK + j * 16) * 136 + k0 + bKoff) * 2);
            #pragma unroll
            for (int mi = 0; mi < 2; mi++)
                #pragma unroll
                for (int nb = 0; nb < 8; nb++)
                    mma16(acc1[mi][nb], af[mi], bf[nb]);
        }

        // scale
        #pragma unroll
        for (int mi = 0; mi < 2; mi++)
            #pragma unroll
            for (int nb = 0; nb < 8; nb++)
                #pragma unroll
                for (int r = 0; r < 4; r++) acc1[mi][nb][r] *= scale;

        // ---- register softmax over 256 cols ----
        float mx[4] = {-1e30f, -1e30f, -1e30f, -1e30f};
        #pragma unroll
        for (int mi = 0; mi < 2; mi++)
            #pragma unroll
            for (int nb = 0; nb < 8; nb++) {
                mx[2 * mi]     = fmaxf(mx[2 * mi],     fmaxf(acc1[mi][nb][0], acc1[mi][nb][1]));
                mx[2 * mi + 1] = fmaxf(mx[2 * mi + 1], fmaxf(acc1[mi][nb][2], acc1[mi][nb][3]));
            }
        #pragma unroll
        for (int o = 1; o <= 2; o <<= 1)
            #pragma unroll
            for (int i = 0; i < 4; i++)
                mx[i] = fmaxf(mx[i], __shfl_xor_sync(0xffffffffu, mx[i], o));
        if (tg == 0) {
            #pragma unroll
            for (int i = 0; i < 4; i++) {
                int r = wm * 32 + (i >> 1) * 16 + (i & 1) * 8 + g;
                redm[wn * 128 + r] = mx[i];
            }
        }
        __syncthreads();
        float fm[4];
        #pragma unroll
        for (int i = 0; i < 4; i++) {
            int r = wm * 32 + (i >> 1) * 16 + (i & 1) * 8 + g;
            fm[i] = fmaxf(fmaxf(redm[r], redm[128 + r]), fmaxf(redm[256 + r], redm[384 + r]));
        }
        float sum[4] = {0.f, 0.f, 0.f, 0.f};
        #pragma unroll
        for (int mi = 0; mi < 2; mi++)
            #pragma unroll
            for (int nb = 0; nb < 8; nb++) {
                acc1[mi][nb][0] = __expf(acc1[mi][nb][0] - fm[2 * mi]);
                acc1[mi][nb][1] = __expf(acc1[mi][nb][1] - fm[2 * mi]);
                acc1[mi][nb][2] = __expf(acc1[mi][nb][2] - fm[2 * mi + 1]);
                acc1[mi][nb][3] = __expf(acc1[mi][nb][3] - fm[2 * mi + 1]);
                sum[2 * mi]     += acc1[mi][nb][0] + acc1[mi][nb][1];
                sum[2 * mi + 1] += acc1[mi][nb][2] + acc1[mi][nb][3];
            }
        #pragma unroll
        for (int o = 1; o <= 2; o <<= 1)
            #pragma unroll
            for (int i = 0; i < 4; i++)
                sum[i] += __shfl_xor_sync(0xffffffffu, sum[i], o);
        if (tg == 0) {
            #pragma unroll
            for (int i = 0; i < 4; i++) {
                int r = wm * 32 + (i >> 1) * 16 + (i & 1) * 8 + g;
                reds[wn * 128 + r] = sum[i];
            }
        }
        __syncthreads();
        float inv[4];
        #pragma unroll
        for (int i = 0; i < 4; i++) {
            int r = wm * 32 + (i >> 1) * 16 + (i & 1) * 8 + g;
            inv[i] = 1.f / (reds[r] + reds[128 + r] + reds[256 + r] + reds[384 + r]);
        }
        // write P (half) to Ps (Q reads are done: both syncs above passed)
        #pragma unroll
        for (int mi = 0; mi < 2; mi++) {
            int r0 = wm * 32 + mi * 16 + g;
            #pragma unroll
            for (int nb = 0; nb < 8; nb++) {
                int col = wn * 64 + nb * 8 + 2 * tg;
                *(uint32_t*)&Ps[r0 * 264 + col] =
                    f2h2(acc1[mi][nb][0] * inv[2 * mi], acc1[mi][nb][1] * inv[2 * mi]);
                *(uint32_t*)&Ps[(r0 + 8) * 264 + col] =
                    f2h2(acc1[mi][nb][2] * inv[2 * mi + 1], acc1[mi][nb][3] * inv[2 * mi + 1]);
            }
        }
        __syncthreads();

        // ---- GEMM2: O[128,128] = P @ V (all smem, ldmatrix, no syncs) ----
        float acc2[2][4][4];
        #pragma unroll
        for (int i = 0; i < 2; i++)
            #pragma unroll
            for (int j = 0; j < 4; j++)
                #pragma unroll
                for (int r = 0; r < 4; r++) acc2[i][j][r] = 0.f;

        #pragma unroll 4
        for (int kc = 0; kc < 16; kc++) {
            int k0 = kc * 16;
            uint32_t af[2][4], bf[4][2];
            #pragma unroll
            for (int mi = 0; mi < 2; mi++)
                ldsm4(af[mi][0], af[mi][1], af[mi][2], af[mi][3],
                      ps_b + ((aRow + mi * 16) * 264 + k0 + aKoff) * 2);
            #pragma unroll
            for (int nh = 0; nh < 2; nh++)
                ldsm4t(bf[2 * nh][0], bf[2 * nh][1], bf[2 * nh + 1][0], bf[2 * nh + 1][1],
                       vs_b + ((k0 + vRow) * 136 + vColB + nh * 16) * 2);
            #pragma unroll
            for (int mi = 0; mi < 2; mi++)
                #pragma unroll
                for (int nb = 0; nb < 4; nb++)
                    mma16(acc2[mi][nb], af[mi], bf[nb]);
        }

        // epilogue: fp32 store out[b, c, h, w]
        #pragma unroll
        for (int mi = 0; mi < 2; mi++) {
            int m = wm * 32 + mi * 16 + g;
            #pragma unroll
            for (int nb = 0; nb < 4; nb++) {
                int n = wn * 32 + nb * 8 + tg * 2;
                *(float2*)(Og + (size_t)(c0 + m) * HWn + n) =
                    make_float2(acc2[mi][nb][0], acc2[mi][nb][1]);
                *(float2*)(Og + (size_t)(c0 + m + 8) * HWn + n) =
                    make_float2(acc2[mi][nb][2], acc2[mi][nb][3]);
            }
        }
    }
}

// ---------------------------------------------------------------------------
extern "C" void kernel_launch(void* const* d_in, const int* in_sizes, int n_in,
                              void* d_out, int out_size)
{
    (void)in_sizes; (void)n_in; (void)out_size;
    const float* hidden = (const float*)d_in[0];
    const float* ctx    = (const float*)d_in[1];
    const float* qdw = (const float*)d_in[2];
    const float* qdb = (const float*)d_in[3];
    const float* qpw = (const float*)d_in[4];
    const float* qpb = (const float*)d_in[5];
    const float* kdw = (const float*)d_in[6];
    const float* kdb = (const float*)d_in[7];
    const float* kpw = (const float*)d_in[8];
    const float* kpb = (const float*)d_in[9];
    const float* vdw = (const float*)d_in[10];
    const float* vdb = (const float*)d_in[11];
    const float* vpw = (const float*)d_in[12];
    const float* vpb = (const float*)d_in[13];
    float* out = (float*)d_out;

    k_wconv<<<dim3(128, 3), 256>>>(qpw, kpw, vpw);
    k_dwconv<<<dim3(Hn / 16, Bn * Cn), 256>>>(hidden, ctx, qdw, qdb, kdw, kdb, vdw, vdb);

    cudaFuncSetAttribute(k_pointwise, cudaFuncAttributeMaxDynamicSharedMemorySize, PW_SMEM);
    k_pointwise<<<dim3(2, HWn / 128, 24), 256, PW_SMEM>>>(qpb, kpb, vpb);

    cudaFuncSetAttribute(k_attn, cudaFuncAttributeMaxDynamicSharedMemorySize, K3_SMEM);
    k_attn<<<Bn * Hn, 512, K3_SMEM>>>(out);
}

// round 12
// speedup vs baseline: 2.4423x; 1.0234x over previous
#include <cuda_runtime.h>
#include <cuda_fp16.h>
#include <cstdint>
#include <cstddef>

// ---------------------------------------------------------------------------
// CrossAttention_41497974014052  (sm_103a, legacy mma path)
// K0: W fp32 -> half pre-convert
// K1: depthwise3x3 (smem-tiled, half2 stores)
// K2: pointwise GEMM, fp16 m16n8k16, cp.async 3-stage, ldmatrix frags
//     (q output pre-scaled by 1/sqrt(32))
// K3: per-(b,h) channel attention: K/Q then V split-group cp.async prologue,
//     all-ldmatrix frags, register softmax, zero-sync GEMM inner loops
// ---------------------------------------------------------------------------

constexpr int Bn = 8, Cn = 256, Hn = 128, Wn = 128;
constexpr int HWn = Hn * Wn;                    // 16384
constexpr size_t CHWn = (size_t)Cn * HWn;       // 4194304
constexpr size_t IMG  = (size_t)Bn * CHWn;      // 33554432

__device__ __half g_y[3 * IMG];
__device__ __half g_qkv[3 * IMG];
__device__ __half g_wh[3 * 65536];

__device__ __forceinline__ uint32_t f2h2(float a, float b) {
    __half2 h = __floats2half2_rn(a, b);
    return *reinterpret_cast<uint32_t*>(&h);
}
__device__ __forceinline__ uint32_t smem_u32(const void* p) {
    uint32_t a;
    asm("{ .reg .u64 t; cvta.to.shared.u64 t, %1; cvt.u32.u64 %0, t; }" : "=r"(a) : "l"(p));
    return a;
}
__device__ __forceinline__ void mma16(float d[4], const uint32_t a[4], const uint32_t b[2]) {
    asm volatile(
        "mma.sync.aligned.m16n8k16.row.col.f32.f16.f16.f32 "
        "{%0,%1,%2,%3}, {%4,%5,%6,%7}, {%8,%9}, {%0,%1,%2,%3};\n"
        : "+f"(d[0]), "+f"(d[1]), "+f"(d[2]), "+f"(d[3])
        : "r"(a[0]), "r"(a[1]), "r"(a[2]), "r"(a[3]), "r"(b[0]), "r"(b[1]));
}
__device__ __forceinline__ void ldsm4(uint32_t& r0, uint32_t& r1, uint32_t& r2, uint32_t& r3,
                                      uint32_t addr) {
    asm volatile("ldmatrix.sync.aligned.m8n8.x4.shared.b16 {%0,%1,%2,%3}, [%4];"
                 : "=r"(r0), "=r"(r1), "=r"(r2), "=r"(r3) : "r"(addr));
}
__device__ __forceinline__ void ldsm4t(uint32_t& r0, uint32_t& r1, uint32_t& r2, uint32_t& r3,
                                       uint32_t addr) {
    asm volatile("ldmatrix.sync.aligned.m8n8.x4.trans.shared.b16 {%0,%1,%2,%3}, [%4];"
                 : "=r"(r0), "=r"(r1), "=r"(r2), "=r"(r3) : "r"(addr));
}
__device__ __forceinline__ void cp16(uint32_t dst, const void* src) {
    asm volatile("cp.async.cg.shared.global [%0], [%1], 16;"
                 :: "r"(dst), "l"((size_t)__cvta_generic_to_global(src)) : "memory");
}
#define CP_COMMIT() asm volatile("cp.async.commit_group;" ::: "memory")
#define CP_WAIT1()  asm volatile("cp.async.wait_group 1;" ::: "memory")
#define CP_WAIT0()  asm volatile("cp.async.wait_group 0;" ::: "memory")

// ---------------------------------------------------------------------------
// Kernel 0: W fp32 -> half. grid (128, 3), 256 thr.
// ---------------------------------------------------------------------------
__global__ void k_wconv(const float* __restrict__ qpw, const float* __restrict__ kpw,
                        const float* __restrict__ vpw)
{
    int t = blockIdx.y;
    const float* W = (t == 0) ? qpw : (t == 1) ? kpw : vpw;
    int i = (blockIdx.x * 256 + threadIdx.x) * 2;
    float2 v = *(const float2*)(W + i);
    *(__half2*)(g_wh + t * 65536 + i) = __floats2half2_rn(v.x, v.y);
}

// ---------------------------------------------------------------------------
// Kernel 1: depthwise 3x3 (SAME) + bias, smem-tiled, 2 cols/thread (half2 out)
// grid (H/16, B*C), 256 threads.
// ---------------------------------------------------------------------------
__global__ void __launch_bounds__(256)
k_dwconv(const float* __restrict__ hidden, const float* __restrict__ ctx,
         const float* __restrict__ qw, const float* __restrict__ qb,
         const float* __restrict__ kw, const float* __restrict__ kb,
         const float* __restrict__ vw, const float* __restrict__ vb)
{
    __shared__ float shH[18][132];
    __shared__ float shC[18][132];

    int h0 = blockIdx.x * 16;
    int bc = blockIdx.y;
    int c  = bc & (Cn - 1);
    int tid = threadIdx.x;
    size_t base = (size_t)bc * HWn;
    const float* xh = hidden + base;
    const float* xc = ctx + base;

    for (int idx = tid; idx < 18 * 130; idx += 256) {
        int r = idx / 130, ci = idx - r * 130;
        int hh = h0 + r - 1, ww = ci - 1;
        bool ok = ((unsigned)hh < (unsigned)Hn) & ((unsigned)ww < (unsigned)Wn);
        float vh = 0.f, vc = 0.f;
        if (ok) { int o = hh * Wn + ww; vh = xh[o]; vc = xc[o]; }
        shH[r][ci] = vh;
        shC[r][ci] = vc;
    }

    float wq[9], wk[9], wv[9];
    #pragma unroll
    for (int i = 0; i < 9; i++) {
        wq[i] = qw[c * 9 + i]; wk[i] = kw[c * 9 + i]; wv[i] = vw[c * 9 + i];
    }
    float bq = qb[c], bk = kb[c], bv = vb[c];
    __syncthreads();

    int w2 = (tid & 63) * 2;
    int rb = (tid >> 6) * 4;

    float A0[4], A1[4], A2[4], B0[4], B1[4], B2[4];
    #pragma unroll
    for (int j = 0; j < 4; j++) {
        A0[j] = shH[rb][w2 + j];     A1[j] = shH[rb + 1][w2 + j];
        B0[j] = shC[rb][w2 + j];     B1[j] = shC[rb + 1][w2 + j];
    }

    #pragma unroll
    for (int rr = 0; rr < 4; rr++) {
        #pragma unroll
        for (int j = 0; j < 4; j++) {
            A2[j] = shH[rb + rr + 2][w2 + j];
            B2[j] = shC[rb + rr + 2][w2 + j];
        }
        float aq0 = bq, aq1 = bq, ak0 = bk, ak1 = bk, av0 = bv, av1 = bv;
        #pragma unroll
        for (int j = 0; j < 3; j++) {
            aq0 += wq[j] * A0[j]     + wq[3 + j] * A1[j]     + wq[6 + j] * A2[j];
            aq1 += wq[j] * A0[j + 1] + wq[3 + j] * A1[j + 1] + wq[6 + j] * A2[j + 1];
            ak0 += wk[j] * B0[j]     + wk[3 + j] * B1[j]     + wk[6 + j] * B2[j];
            ak1 += wk[j] * B0[j + 1] + wk[3 + j] * B1[j + 1] + wk[6 + j] * B2[j + 1];
            av0 += wv[j] * B0[j]     + wv[3 + j] * B1[j]     + wv[6 + j] * B2[j];
            av1 += wv[j] * B0[j + 1] + wv[3 + j] * B1[j + 1] + wv[6 + j] * B2[j + 1];
        }
        size_t o = base + (size_t)(h0 + rb + rr) * Wn + w2;
        *(__half2*)(g_y + o)           = __floats2half2_rn(aq0, aq1);
        *(__half2*)(g_y + IMG + o)     = __floats2half2_rn(ak0, ak1);
        *(__half2*)(g_y + 2 * IMG + o) = __floats2half2_rn(av0, av1);
        #pragma unroll
        for (int j = 0; j < 4; j++) {
            A0[j] = A1[j]; A1[j] = A2[j];
            B0[j] = B1[j]; B1[j] = B2[j];
        }
    }
}

// ---------------------------------------------------------------------------
// Kernel 2: pointwise GEMM  D[o][s] = sum_c W[o][c] * y[c][s] + bias[o]
// fp16 m16n8k16, CTA 128x128, K=256 in 8 chunks of 32, cp.async 3-stage.
// 256 thr = 8 warps (2M x 4N), warp tile 64x32, ldmatrix frags.
// q output (t==0) is pre-scaled by 1/sqrt(32) so K3 skips the scale pass.
// grid (2, 128, 24)
// ---------------------------------------------------------------------------
constexpr int PW_AS_STRIDE = 128 * 40 * 2;   // 10240
constexpr int PW_BS_BASE   = 3 * PW_AS_STRIDE;
constexpr int PW_BS_STRIDE = 32 * 136 * 2;   // 8704
constexpr int PW_SMEM      = PW_BS_BASE + 3 * PW_BS_STRIDE;  // 56832

__global__ void __launch_bounds__(256, 2)
k_pointwise(const float* __restrict__ qpb, const float* __restrict__ kpb,
            const float* __restrict__ vpb)
{
    extern __shared__ __align__(16) char dyn[];
    uint32_t sb = smem_u32(dyn);

    int mt = blockIdx.x, nt = blockIdx.y, tb = blockIdx.z;
    int t = tb >> 3, b = tb & 7;
    const float* bias = (t == 0) ? qpb : (t == 1) ? kpb : vpb;
    const float oscale = (t == 0) ? 0.17677669529663687f : 1.0f;   // 1/sqrt(32) folded into q
    const __half* Wh = g_wh + t * 65536;
    const __half* Yt = g_y  + (size_t)t * IMG + (size_t)b * CHWn;
    __half*       Cm = g_qkv + (size_t)t * IMG + (size_t)b * CHWn;
    int m0 = mt * 128, n0 = nt * 128;

    int tid = threadIdx.x, lane = tid & 31, warp = tid >> 5;
    int wm = warp >> 2, wn = warp & 3, g = lane >> 2, tg = lane & 3;

    int rA = tid >> 1, cA = (tid & 1) * 16;   // A: 128 x 32
    int rB = tid >> 3, cB = (tid & 7) * 16;   // B: 32 x 128

    // ldmatrix lane geometry
    int aRow = wm * 64 + (lane & 15);         // + mi*16, pitch 40
    int aKoff = (lane >> 4) * 8;              // + kk

    auto issue = [&](int stage) {
        int buf = stage % 3;
        int k0 = stage * 32;
        uint32_t asb = sb + buf * PW_AS_STRIDE;
        uint32_t bsb = sb + PW_BS_BASE + buf * PW_BS_STRIDE;
        const __half* srcA = Wh + (size_t)(m0 + rA) * Cn + k0 + cA;
        cp16(asb + (rA * 40 + cA) * 2, srcA);
        cp16(asb + (rA * 40 + cA + 8) * 2, srcA + 8);
        const __half* srcB = Yt + (size_t)(k0 + rB) * HWn + n0 + cB;
        cp16(bsb + (rB * 136 + cB) * 2, srcB);
        cp16(bsb + (rB * 136 + cB + 8) * 2, srcB + 8);
        CP_COMMIT();
    };

    float acc[4][4][4];
    #pragma unroll
    for (int i = 0; i < 4; i++)
        #pragma unroll
        for (int j = 0; j < 4; j++)
            #pragma unroll
            for (int r = 0; r < 4; r++) acc[i][j][r] = 0.f;

    issue(0);
    issue(1);

    for (int kc = 0; kc < 8; kc++) {
        if (kc < 7) { CP_WAIT1(); } else { CP_WAIT0(); }
        __syncthreads();
        if (kc + 2 < 8) issue(kc + 2);

        int buf = kc % 3;
        uint32_t asb = sb + buf * PW_AS_STRIDE;
        uint32_t bsb = sb + PW_BS_BASE + buf * PW_BS_STRIDE;

        #pragma unroll
        for (int kk = 0; kk < 32; kk += 16) {
            uint32_t af[4][4], bfm[4][2];
            #pragma unroll
            for (int mi = 0; mi < 4; mi++)
                ldsm4(af[mi][0], af[mi][1], af[mi][2], af[mi][3],
                      asb + ((aRow + mi * 16) * 40 + kk + aKoff) * 2);
            #pragma unroll
            for (int nh = 0; nh < 2; nh++) {
                int lrow = kk + (lane & 15);
                int lcol = wn * 32 + nh * 16 + (lane >> 4) * 8;
                ldsm4t(bfm[2 * nh][0], bfm[2 * nh][1], bfm[2 * nh + 1][0], bfm[2 * nh + 1][1],
                       bsb + (lrow * 136 + lcol) * 2);
            }
            #pragma unroll
            for (int mi = 0; mi < 4; mi++)
                #pragma unroll
                for (int nb = 0; nb < 4; nb++)
                    mma16(acc[mi][nb], af[mi], bfm[nb]);
        }
    }

    #pragma unroll
    for (int mi = 0; mi < 4; mi++) {
        int m = m0 + wm * 64 + mi * 16 + g;
        float b0v = bias[m], b1v = bias[m + 8];
        #pragma unroll
        for (int nb = 0; nb < 4; nb++) {
            int n = n0 + wn * 32 + nb * 8 + tg * 2;
            *(__half2*)(Cm + (size_t)m * HWn + n) =
                __floats2half2_rn((acc[mi][nb][0] + b0v) * oscale, (acc[mi][nb][1] + b0v) * oscale);
            *(__half2*)(Cm + (size_t)(m + 8) * HWn + n) =
                __floats2half2_rn((acc[mi][nb][2] + b1v) * oscale, (acc[mi][nb][3] + b1v) * oscale);
        }
    }
}

// ---------------------------------------------------------------------------
// Kernel 3: per-(b,h) channel attention.
//   Prologue: K+Q in cp.async group 0, V in group 1 -> GEMM1 overlaps V load.
//   All frags via ldmatrix. Register softmax. Zero-sync GEMM loops.
// CTA = 1 (b,h), 512 threads (16 warps, 4M x 4N), 2 q-tiles of 128 rows.
// smem: Ps/Qs 128x264 half | Ks 256x136 | Vs 256x136 | red 2x4x128 f32
// ---------------------------------------------------------------------------
constexpr int K3_PS   = 0;
constexpr int K3_KS   = 128 * 264 * 2;            // 67584
constexpr int K3_VS   = K3_KS + 256 * 136 * 2;    // 137216
constexpr int K3_RED  = K3_VS + 256 * 136 * 2;    // 206848
constexpr int K3_SMEM = K3_RED + 2 * 4 * 128 * 4; // 210944

__global__ void __launch_bounds__(512)
k_attn(float* __restrict__ out)
{
    extern __shared__ __align__(16) char smraw[];
    __half* Ps = (__half*)(smraw + K3_PS);    // P: pitch 264 / Q: pitch 136
    float*  redm = (float*)(smraw + K3_RED);  // [4][128]
    float*  reds = redm + 512;                // [4][128]
    uint32_t sb   = smem_u32(smraw);
    uint32_t qs_b = sb + K3_PS;               // Q staging (pitch 136)
    uint32_t ps_b = sb + K3_PS;               // P (pitch 264)
    uint32_t ks_b = sb + K3_KS;
    uint32_t vs_b = sb + K3_VS;

    int bh = blockIdx.x;
    int b = bh >> 7, h = bh & 127;
    const __half* Qg = g_qkv + (size_t)b * CHWn + (size_t)h * Wn;  // [c][w]
    const __half* Kg = Qg + IMG;
    const __half* Vg = Qg + 2 * IMG;
    float* Og = out + (size_t)b * CHWn + (size_t)h * Wn;

    int tid = threadIdx.x;
    int lane = tid & 31, warp = tid >> 5;
    int g = lane >> 2, tg = lane & 3;
    int wm = warp >> 2, wn = warp & 3;

    // ldmatrix lane geometry (precomputed)
    int aRow  = wm * 32 + (lane & 15);        // A frags: + mi*16
    int aKoff = (lane >> 4) * 8;
    int bRowK = wn * 64 + ((lane >> 4) & 1) * 8 + (lane & 7);  // GEMM1 B: + j*16
    int bKoff = ((lane >> 3) & 1) * 8;
    int vRow  = lane & 15;                    // GEMM2 B (trans): + k0
    int vColB = wn * 32 + (lane >> 4) * 8;    // + nh*16

    auto loadQ = [&](int c0) {
        #pragma unroll
        for (int i = 0; i < 4; i++) {
            int chunk = tid + i * 512;        // 0..2047
            int row = chunk >> 4, col = (chunk & 15) * 8;
            cp16(qs_b + (row * 136 + col) * 2, Qg + (size_t)(c0 + row) * HWn + col);
        }
    };

    // ---- prologue: group0 = K + Q(qt=0); group1 = V. GEMM1 starts after g0. ----
    #pragma unroll
    for (int i = 0; i < 8; i++) {
        int chunk = tid + i * 512;            // 0..4095
        int row = chunk >> 4, col = (chunk & 15) * 8;
        cp16(ks_b + (row * 136 + col) * 2, Kg + (size_t)row * HWn + col);
    }
    loadQ(0);
    CP_COMMIT();
    #pragma unroll
    for (int i = 0; i < 8; i++) {
        int chunk = tid + i * 512;
        int row = chunk >> 4, col = (chunk & 15) * 8;
        cp16(vs_b + (row * 136 + col) * 2, Vg + (size_t)row * HWn + col);
    }
    CP_COMMIT();
    CP_WAIT1();          // K + Q resident; V still in flight
    __syncthreads();

    for (int qt = 0; qt < 2; qt++) {
        int c0 = qt * 128;
        if (qt == 1) {
            __syncthreads();     // all Ps (P of qt0) reads done
            loadQ(c0);
            CP_COMMIT();
            CP_WAIT0();
            __syncthreads();
        }

        // ---- GEMM1: S[128,256] = (Q*scale) @ K^T (all smem, ldmatrix) ----
        float acc1[2][8][4];
        #pragma unroll
        for (int i = 0; i < 2; i++)
            #pragma unroll
            for (int j = 0; j < 8; j++)
                #pragma unroll
                for (int r = 0; r < 4; r++) acc1[i][j][r] = 0.f;

        #pragma unroll
        for (int kc = 0; kc < 8; kc++) {
            int k0 = kc * 16;
            uint32_t af[2][4], bf[8][2];
            #pragma unroll
            for (int mi = 0; mi < 2; mi++)
                ldsm4(af[mi][0], af[mi][1], af[mi][2], af[mi][3],
                      qs_b + ((aRow + mi * 16) * 136 + k0 + aKoff) * 2);
            #pragma unroll
            for (int j = 0; j < 4; j++)
                ldsm4(bf[2 * j][0], bf[2 * j][1], bf[2 * j + 1][0], bf[2 * j + 1][1],
                      ks_b + ((bRowK + j * 16) * 136 + k0 + bKoff) * 2);
            #pragma unroll
            for (int mi = 0; mi < 2; mi++)
                #pragma unroll
                for (int nb = 0; nb < 8; nb++)
                    mma16(acc1[mi][nb], af[mi], bf[nb]);
        }

        // ---- register softmax over 256 cols (scale already folded into Q) ----
        float mx[4] = {-1e30f, -1e30f, -1e30f, -1e30f};
        #pragma unroll
        for (int mi = 0; mi < 2; mi++)
            #pragma unroll
            for (int nb = 0; nb < 8; nb++) {
                mx[2 * mi]     = fmaxf(mx[2 * mi],     fmaxf(acc1[mi][nb][0], acc1[mi][nb][1]));
                mx[2 * mi + 1] = fmaxf(mx[2 * mi + 1], fmaxf(acc1[mi][nb][2], acc1[mi][nb][3]));
            }
        #pragma unroll
        for (int o = 1; o <= 2; o <<= 1)
            #pragma unroll
            for (int i = 0; i < 4; i++)
                mx[i] = fmaxf(mx[i], __shfl_xor_sync(0xffffffffu, mx[i], o));
        if (tg == 0) {
            #pragma unroll
            for (int i = 0; i < 4; i++) {
                int r = wm * 32 + (i >> 1) * 16 + (i & 1) * 8 + g;
                redm[wn * 128 + r] = mx[i];
            }
        }
        __syncthreads();
        float fm[4];
        #pragma unroll
        for (int i = 0; i < 4; i++) {
            int r = wm * 32 + (i >> 1) * 16 + (i & 1) * 8 + g;
            fm[i] = fmaxf(fmaxf(redm[r], redm[128 + r]), fmaxf(redm[256 + r], redm[384 + r]));
        }
        float sum[4] = {0.f, 0.f, 0.f, 0.f};
        #pragma unroll
        for (int mi = 0; mi < 2; mi++)
            #pragma unroll
            for (int nb = 0; nb < 8; nb++) {
                acc1[mi][nb][0] = __expf(acc1[mi][nb][0] - fm[2 * mi]);
                acc1[mi][nb][1] = __expf(acc1[mi][nb][1] - fm[2 * mi]);
                acc1[mi][nb][2] = __expf(acc1[mi][nb][2] - fm[2 * mi + 1]);
                acc1[mi][nb][3] = __expf(acc1[mi][nb][3] - fm[2 * mi + 1]);
                sum[2 * mi]     += acc1[mi][nb][0] + acc1[mi][nb][1];
                sum[2 * mi + 1] += acc1[mi][nb][2] + acc1[mi][nb][3];
            }
        #pragma unroll
        for (int o = 1; o <= 2; o <<= 1)
            #pragma unroll
            for (int i = 0; i < 4; i++)
                sum[i] += __shfl_xor_sync(0xffffffffu, sum[i], o);
        if (tg == 0) {
            #pragma unroll
            for (int i = 0; i < 4; i++) {
                int r = wm * 32 + (i >> 1) * 16 + (i & 1) * 8 + g;
                reds[wn * 128 + r] = sum[i];
            }
        }
        __syncthreads();
        float inv[4];
        #pragma unroll
        for (int i = 0; i < 4; i++) {
            int r = wm * 32 + (i >> 1) * 16 + (i & 1) * 8 + g;
            inv[i] = 1.f / (reds[r] + reds[128 + r] + reds[256 + r] + reds[384 + r]);
        }
        // write P (half) to Ps (Q reads are done: both syncs above passed)
        #pragma unroll
        for (int mi = 0; mi < 2; mi++) {
            int r0 = wm * 32 + mi * 16 + g;
            #pragma unroll
            for (int nb = 0; nb < 8; nb++) {
                int col = wn * 64 + nb * 8 + 2 * tg;
                *(uint32_t*)&Ps[r0 * 264 + col] =
                    f2h2(acc1[mi][nb][0] * inv[2 * mi], acc1[mi][nb][1] * inv[2 * mi]);
                *(uint32_t*)&Ps[(r0 + 8) * 264 + col] =
                    f2h2(acc1[mi][nb][2] * inv[2 * mi + 1], acc1[mi][nb][3] * inv[2 * mi + 1]);
            }
        }
        CP_WAIT0();          // V resident (no-op for qt=1)
        __syncthreads();

        // ---- GEMM2: O[128,128] = P @ V (all smem, ldmatrix, no syncs) ----
        float acc2[2][4][4];
        #pragma unroll
        for (int i = 0; i < 2; i++)
            #pragma unroll
            for (int j = 0; j < 4; j++)
                #pragma unroll
                for (int r = 0; r < 4; r++) acc2[i][j][r] = 0.f;

        #pragma unroll 4
        for (int kc = 0; kc < 16; kc++) {
            int k0 = kc * 16;
            uint32_t af[2][4], bf[4][2];
            #pragma unroll
            for (int mi = 0; mi < 2; mi++)
                ldsm4(af[mi][0], af[mi][1], af[mi][2], af[mi][3],
                      ps_b + ((aRow + mi * 16) * 264 + k0 + aKoff) * 2);
            #pragma unroll
            for (int nh = 0; nh < 2; nh++)
                ldsm4t(bf[2 * nh][0], bf[2 * nh][1], bf[2 * nh + 1][0], bf[2 * nh + 1][1],
                       vs_b + ((k0 + vRow) * 136 + vColB + nh * 16) * 2);
            #pragma unroll
            for (int mi = 0; mi < 2; mi++)
                #pragma unroll
                for (int nb = 0; nb < 4; nb++)
                    mma16(acc2[mi][nb], af[mi], bf[nb]);
        }

        // epilogue: fp32 store out[b, c, h, w]
        #pragma unroll
        for (int mi = 0; mi < 2; mi++) {
            int m = wm * 32 + mi * 16 + g;
            #pragma unroll
            for (int nb = 0; nb < 4; nb++) {
                int n = wn * 32 + nb * 8 + tg * 2;
                *(float2*)(Og + (size_t)(c0 + m) * HWn + n) =
                    make_float2(acc2[mi][nb][0], acc2[mi][nb][1]);
                *(float2*)(Og + (size_t)(c0 + m + 8) * HWn + n) =
                    make_float2(acc2[mi][nb][2], acc2[mi][nb][3]);
            }
        }
    }
}

// ---------------------------------------------------------------------------
extern "C" void kernel_launch(void* const* d_in, const int* in_sizes, int n_in,
                              void* d_out, int out_size)
{
    (void)in_sizes; (void)n_in; (void)out_size;
    const float* hidden = (const float*)d_in[0];
    const float* ctx    = (const float*)d_in[1];
    const float* qdw = (const float*)d_in[2];
    const float* qdb = (const float*)d_in[3];
    const float* qpw = (const float*)d_in[4];
    const float* qpb = (const float*)d_in[5];
    const float* kdw = (const float*)d_in[6];
    const float* kdb = (const float*)d_in[7];
    const float* kpw = (const float*)d_in[8];
    const float* kpb = (const float*)d_in[9];
    const float* vdw = (const float*)d_in[10];
    const float* vdb = (const float*)d_in[11];
    const float* vpw = (const float*)d_in[12];
    const float* vpb = (const float*)d_in[13];
    float* out = (float*)d_out;

    k_wconv<<<dim3(128, 3), 256>>>(qpw, kpw, vpw);
    k_dwconv<<<dim3(Hn / 16, Bn * Cn), 256>>>(hidden, ctx, qdw, qdb, kdw, kdb, vdw, vdb);

    cudaFuncSetAttribute(k_pointwise, cudaFuncAttributeMaxDynamicSharedMemorySize, PW_SMEM);
    k_pointwise<<<dim3(2, HWn / 128, 24), 256, PW_SMEM>>>(qpb, kpb, vpb);

    cudaFuncSetAttribute(k_attn, cudaFuncAttributeMaxDynamicSharedMemorySize, K3_SMEM);
    k_attn<<<Bn * Hn, 512, K3_SMEM>>>(out);
}

// round 13
// speedup vs baseline: 2.4842x; 1.0172x over previous
#include <cuda_runtime.h>
#include <cuda_fp16.h>
#include <cstdint>
#include <cstddef>

// ---------------------------------------------------------------------------
// CrossAttention_41497974014052  (sm_103a, legacy mma path)
// K0: W fp32 -> half pre-convert
// K1: depthwise3x3 (smem-tiled, half2 stores)
// K2: pointwise GEMM, fp16 m16n8k16, cp.async 3-stage, ldmatrix frags
//     (q output pre-scaled by 1/sqrt(32))
// K3: per-(b,h) channel attention, FlashAttention-2 style:
//     one warp owns 16 S-rows end-to-end; online softmax over 4 d-blocks;
//     P passes mma->mma through registers (f2h2 -> A-frags); 2 barriers total.
// ---------------------------------------------------------------------------

constexpr int Bn = 8, Cn = 256, Hn = 128, Wn = 128;
constexpr int HWn = Hn * Wn;                    // 16384
constexpr size_t CHWn = (size_t)Cn * HWn;       // 4194304
constexpr size_t IMG  = (size_t)Bn * CHWn;      // 33554432

__device__ __half g_y[3 * IMG];
__device__ __half g_qkv[3 * IMG];
__device__ __half g_wh[3 * 65536];

__device__ __forceinline__ uint32_t f2h2(float a, float b) {
    __half2 h = __floats2half2_rn(a, b);
    return *reinterpret_cast<uint32_t*>(&h);
}
__device__ __forceinline__ uint32_t smem_u32(const void* p) {
    uint32_t a;
    asm("{ .reg .u64 t; cvta.to.shared.u64 t, %1; cvt.u32.u64 %0, t; }" : "=r"(a) : "l"(p));
    return a;
}
__device__ __forceinline__ void mma16(float d[4], const uint32_t a[4], const uint32_t b[2]) {
    asm volatile(
        "mma.sync.aligned.m16n8k16.row.col.f32.f16.f16.f32 "
        "{%0,%1,%2,%3}, {%4,%5,%6,%7}, {%8,%9}, {%0,%1,%2,%3};\n"
        : "+f"(d[0]), "+f"(d[1]), "+f"(d[2]), "+f"(d[3])
        : "r"(a[0]), "r"(a[1]), "r"(a[2]), "r"(a[3]), "r"(b[0]), "r"(b[1]));
}
__device__ __forceinline__ void ldsm4(uint32_t& r0, uint32_t& r1, uint32_t& r2, uint32_t& r3,
                                      uint32_t addr) {
    asm volatile("ldmatrix.sync.aligned.m8n8.x4.shared.b16 {%0,%1,%2,%3}, [%4];"
                 : "=r"(r0), "=r"(r1), "=r"(r2), "=r"(r3) : "r"(addr));
}
__device__ __forceinline__ void ldsm4t(uint32_t& r0, uint32_t& r1, uint32_t& r2, uint32_t& r3,
                                       uint32_t addr) {
    asm volatile("ldmatrix.sync.aligned.m8n8.x4.trans.shared.b16 {%0,%1,%2,%3}, [%4];"
                 : "=r"(r0), "=r"(r1), "=r"(r2), "=r"(r3) : "r"(addr));
}
__device__ __forceinline__ void cp16(uint32_t dst, const void* src) {
    asm volatile("cp.async.cg.shared.global [%0], [%1], 16;"
                 :: "r"(dst), "l"((size_t)__cvta_generic_to_global(src)) : "memory");
}
#define CP_COMMIT() asm volatile("cp.async.commit_group;" ::: "memory")
#define CP_WAIT1()  asm volatile("cp.async.wait_group 1;" ::: "memory")
#define CP_WAIT0()  asm volatile("cp.async.wait_group 0;" ::: "memory")

// ---------------------------------------------------------------------------
// Kernel 0: W fp32 -> half. grid (128, 3), 256 thr.
// ---------------------------------------------------------------------------
__global__ void k_wconv(const float* __restrict__ qpw, const float* __restrict__ kpw,
                        const float* __restrict__ vpw)
{
    int t = blockIdx.y;
    const float* W = (t == 0) ? qpw : (t == 1) ? kpw : vpw;
    int i = (blockIdx.x * 256 + threadIdx.x) * 2;
    float2 v = *(const float2*)(W + i);
    *(__half2*)(g_wh + t * 65536 + i) = __floats2half2_rn(v.x, v.y);
}

// ---------------------------------------------------------------------------
// Kernel 1: depthwise 3x3 (SAME) + bias, smem-tiled, 2 cols/thread (half2 out)
// grid (H/16, B*C), 256 threads.
// ---------------------------------------------------------------------------
__global__ void __launch_bounds__(256)
k_dwconv(const float* __restrict__ hidden, const float* __restrict__ ctx,
         const float* __restrict__ qw, const float* __restrict__ qb,
         const float* __restrict__ kw, const float* __restrict__ kb,
         const float* __restrict__ vw, const float* __restrict__ vb)
{
    __shared__ float shH[18][132];
    __shared__ float shC[18][132];

    int h0 = blockIdx.x * 16;
    int bc = blockIdx.y;
    int c  = bc & (Cn - 1);
    int tid = threadIdx.x;
    size_t base = (size_t)bc * HWn;
    const float* xh = hidden + base;
    const float* xc = ctx + base;

    for (int idx = tid; idx < 18 * 130; idx += 256) {
        int r = idx / 130, ci = idx - r * 130;
        int hh = h0 + r - 1, ww = ci - 1;
        bool ok = ((unsigned)hh < (unsigned)Hn) & ((unsigned)ww < (unsigned)Wn);
        float vh = 0.f, vc = 0.f;
        if (ok) { int o = hh * Wn + ww; vh = xh[o]; vc = xc[o]; }
        shH[r][ci] = vh;
        shC[r][ci] = vc;
    }

    float wq[9], wk[9], wv[9];
    #pragma unroll
    for (int i = 0; i < 9; i++) {
        wq[i] = qw[c * 9 + i]; wk[i] = kw[c * 9 + i]; wv[i] = vw[c * 9 + i];
    }
    float bq = qb[c], bk = kb[c], bv = vb[c];
    __syncthreads();

    int w2 = (tid & 63) * 2;
    int rb = (tid >> 6) * 4;

    float A0[4], A1[4], A2[4], B0[4], B1[4], B2[4];
    #pragma unroll
    for (int j = 0; j < 4; j++) {
        A0[j] = shH[rb][w2 + j];     A1[j] = shH[rb + 1][w2 + j];
        B0[j] = shC[rb][w2 + j];     B1[j] = shC[rb + 1][w2 + j];
    }

    #pragma unroll
    for (int rr = 0; rr < 4; rr++) {
        #pragma unroll
        for (int j = 0; j < 4; j++) {
            A2[j] = shH[rb + rr + 2][w2 + j];
            B2[j] = shC[rb + rr + 2][w2 + j];
        }
        float aq0 = bq, aq1 = bq, ak0 = bk, ak1 = bk, av0 = bv, av1 = bv;
        #pragma unroll
        for (int j = 0; j < 3; j++) {
            aq0 += wq[j] * A0[j]     + wq[3 + j] * A1[j]     + wq[6 + j] * A2[j];
            aq1 += wq[j] * A0[j + 1] + wq[3 + j] * A1[j + 1] + wq[6 + j] * A2[j + 1];
            ak0 += wk[j] * B0[j]     + wk[3 + j] * B1[j]     + wk[6 + j] * B2[j];
            ak1 += wk[j] * B0[j + 1] + wk[3 + j] * B1[j + 1] + wk[6 + j] * B2[j + 1];
            av0 += wv[j] * B0[j]     + wv[3 + j] * B1[j]     + wv[6 + j] * B2[j];
            av1 += wv[j] * B0[j + 1] + wv[3 + j] * B1[j + 1] + wv[6 + j] * B2[j + 1];
        }
        size_t o = base + (size_t)(h0 + rb + rr) * Wn + w2;
        *(__half2*)(g_y + o)           = __floats2half2_rn(aq0, aq1);
        *(__half2*)(g_y + IMG + o)     = __floats2half2_rn(ak0, ak1);
        *(__half2*)(g_y + 2 * IMG + o) = __floats2half2_rn(av0, av1);
        #pragma unroll
        for (int j = 0; j < 4; j++) {
            A0[j] = A1[j]; A1[j] = A2[j];
            B0[j] = B1[j]; B1[j] = B2[j];
        }
    }
}

// ---------------------------------------------------------------------------
// Kernel 2: pointwise GEMM  D[o][s] = sum_c W[o][c] * y[c][s] + bias[o]
// fp16 m16n8k16, CTA 128x128, K=256 in 8 chunks of 32, cp.async 3-stage.
// q output (t==0) pre-scaled by 1/sqrt(32).
// grid (2, 128, 24)
// ---------------------------------------------------------------------------
constexpr int PW_AS_STRIDE = 128 * 40 * 2;   // 10240
constexpr int PW_BS_BASE   = 3 * PW_AS_STRIDE;
constexpr int PW_BS_STRIDE = 32 * 136 * 2;   // 8704
constexpr int PW_SMEM      = PW_BS_BASE + 3 * PW_BS_STRIDE;  // 56832

__global__ void __launch_bounds__(256, 2)
k_pointwise(const float* __restrict__ qpb, const float* __restrict__ kpb,
            const float* __restrict__ vpb)
{
    extern __shared__ __align__(16) char dyn[];
    uint32_t sb = smem_u32(dyn);

    int mt = blockIdx.x, nt = blockIdx.y, tb = blockIdx.z;
    int t = tb >> 3, b = tb & 7;
    const float* bias = (t == 0) ? qpb : (t == 1) ? kpb : vpb;
    const float oscale = (t == 0) ? 0.17677669529663687f : 1.0f;
    const __half* Wh = g_wh + t * 65536;
    const __half* Yt = g_y  + (size_t)t * IMG + (size_t)b * CHWn;
    __half*       Cm = g_qkv + (size_t)t * IMG + (size_t)b * CHWn;
    int m0 = mt * 128, n0 = nt * 128;

    int tid = threadIdx.x, lane = tid & 31, warp = tid >> 5;
    int wm = warp >> 2, wn = warp & 3, g = lane >> 2, tg = lane & 3;

    int rA = tid >> 1, cA = (tid & 1) * 16;
    int rB = tid >> 3, cB = (tid & 7) * 16;

    int aRow = wm * 64 + (lane & 15);
    int aKoff = (lane >> 4) * 8;

    auto issue = [&](int stage) {
        int buf = stage % 3;
        int k0 = stage * 32;
        uint32_t asb = sb + buf * PW_AS_STRIDE;
        uint32_t bsb = sb + PW_BS_BASE + buf * PW_BS_STRIDE;
        const __half* srcA = Wh + (size_t)(m0 + rA) * Cn + k0 + cA;
        cp16(asb + (rA * 40 + cA) * 2, srcA);
        cp16(asb + (rA * 40 + cA + 8) * 2, srcA + 8);
        const __half* srcB = Yt + (size_t)(k0 + rB) * HWn + n0 + cB;
        cp16(bsb + (rB * 136 + cB) * 2, srcB);
        cp16(bsb + (rB * 136 + cB + 8) * 2, srcB + 8);
        CP_COMMIT();
    };

    float acc[4][4][4];
    #pragma unroll
    for (int i = 0; i < 4; i++)
        #pragma unroll
        for (int j = 0; j < 4; j++)
            #pragma unroll
            for (int r = 0; r < 4; r++) acc[i][j][r] = 0.f;

    issue(0);
    issue(1);

    for (int kc = 0; kc < 8; kc++) {
        if (kc < 7) { CP_WAIT1(); } else { CP_WAIT0(); }
        __syncthreads();
        if (kc + 2 < 8) issue(kc + 2);

        int buf = kc % 3;
        uint32_t asb = sb + buf * PW_AS_STRIDE;
        uint32_t bsb = sb + PW_BS_BASE + buf * PW_BS_STRIDE;

        #pragma unroll
        for (int kk = 0; kk < 32; kk += 16) {
            uint32_t af[4][4], bfm[4][2];
            #pragma unroll
            for (int mi = 0; mi < 4; mi++)
                ldsm4(af[mi][0], af[mi][1], af[mi][2], af[mi][3],
                      asb + ((aRow + mi * 16) * 40 + kk + aKoff) * 2);
            #pragma unroll
            for (int nh = 0; nh < 2; nh++) {
                int lrow = kk + (lane & 15);
                int lcol = wn * 32 + nh * 16 + (lane >> 4) * 8;
                ldsm4t(bfm[2 * nh][0], bfm[2 * nh][1], bfm[2 * nh + 1][0], bfm[2 * nh + 1][1],
                       bsb + (lrow * 136 + lcol) * 2);
            }
            #pragma unroll
            for (int mi = 0; mi < 4; mi++)
                #pragma unroll
                for (int nb = 0; nb < 4; nb++)
                    mma16(acc[mi][nb], af[mi], bfm[nb]);
        }
    }

    #pragma unroll
    for (int mi = 0; mi < 4; mi++) {
        int m = m0 + wm * 64 + mi * 16 + g;
        float b0v = bias[m], b1v = bias[m + 8];
        #pragma unroll
        for (int nb = 0; nb < 4; nb++) {
            int n = n0 + wn * 32 + nb * 8 + tg * 2;
            *(__half2*)(Cm + (size_t)m * HWn + n) =
                __floats2half2_rn((acc[mi][nb][0] + b0v) * oscale, (acc[mi][nb][1] + b0v) * oscale);
            *(__half2*)(Cm + (size_t)(m + 8) * HWn + n) =
                __floats2half2_rn((acc[mi][nb][2] + b1v) * oscale, (acc[mi][nb][3] + b1v) * oscale);
        }
    }
}

// ---------------------------------------------------------------------------
// Kernel 3: per-(b,h) channel attention, FA2-style.
// 512 threads = 16 warps; warp w owns S-rows [16w, 16w+16) for ALL of
// GEMM1 -> online softmax -> GEMM2. d streamed in 4 blocks of 64.
// P stays in registers (acc -> f2h2 -> A-frags). Barriers: 2 total.
// smem: Qs 256x136 | Ks 256x136 | Vs 256x136 (half)  = 208896 B
// ---------------------------------------------------------------------------
constexpr int K3_QS   = 0;
constexpr int K3_KS   = 256 * 136 * 2;            // 69632
constexpr int K3_VS   = 2 * 256 * 136 * 2;        // 139264
constexpr int K3_SMEM = 3 * 256 * 136 * 2;        // 208896

__global__ void __launch_bounds__(512)
k_attn(float* __restrict__ out)
{
    extern __shared__ __align__(16) char smraw[];
    uint32_t sb   = smem_u32(smraw);
    uint32_t qs_b = sb + K3_QS;
    uint32_t ks_b = sb + K3_KS;
    uint32_t vs_b = sb + K3_VS;

    int bh = blockIdx.x;
    int b = bh >> 7, h = bh & 127;
    const __half* Qg = g_qkv + (size_t)b * CHWn + (size_t)h * Wn;  // [c][w]
    const __half* Kg = Qg + IMG;
    const __half* Vg = Qg + 2 * IMG;
    float* Og = out + (size_t)b * CHWn + (size_t)h * Wn;

    int tid = threadIdx.x;
    int lane = tid & 31, warp = tid >> 5;
    int g = lane >> 2, tg = lane & 3;
    int m0 = warp * 16;                      // this warp's 16 S-rows

    // ldmatrix lane geometry
    int qRow  = m0 + (lane & 15);            // Q A-frags (non-trans)
    int qKoff = (lane >> 4) * 8;
    int kOff  = ((lane >> 4) & 1) * 8 + (lane & 7);   // K B-frags: row = d0 + j*16 + kOff
    int kKoff = ((lane >> 3) & 1) * 8;
    int vRow  = lane & 15;                   // V B-frags (trans): row = d0 + kc*16 + vRow
    int vCol8 = (lane >> 4) * 8;             // col = nv*16 + vCol8

    // ---- prologue: group0 = Q + K; group1 = V ----
    #pragma unroll
    for (int i = 0; i < 8; i++) {
        int chunk = tid + i * 512;            // 0..4095
        int row = chunk >> 4, col = (chunk & 15) * 8;
        cp16(qs_b + (row * 136 + col) * 2, Qg + (size_t)row * HWn + col);
        cp16(ks_b + (row * 136 + col) * 2, Kg + (size_t)row * HWn + col);
    }
    CP_COMMIT();
    #pragma unroll
    for (int i = 0; i < 8; i++) {
        int chunk = tid + i * 512;
        int row = chunk >> 4, col = (chunk & 15) * 8;
        cp16(vs_b + (row * 136 + col) * 2, Vg + (size_t)row * HWn + col);
    }
    CP_COMMIT();
    CP_WAIT1();          // Q + K resident; V still in flight
    __syncthreads();

    // ---- state: O accumulator [16 n8-tiles x 4], online softmax m/l ----
    float O[16][4];
    #pragma unroll
    for (int i = 0; i < 16; i++)
        #pragma unroll
        for (int r = 0; r < 4; r++) O[i][r] = 0.f;
    float mrow0 = -1e30f, mrow1 = -1e30f;    // rows m0+g, m0+8+g
    float lrow0 = 0.f,    lrow1 = 0.f;

    #pragma unroll 1
    for (int db = 0; db < 4; db++) {
        int d0 = db * 64;

        // ---- GEMM1: S_blk[16 x 64] = Q[m0..,:] @ K[d0..d0+63,:]^T ----
        float S[8][4];
        #pragma unroll
        for (int i = 0; i < 8; i++)
            #pragma unroll
            for (int r = 0; r < 4; r++) S[i][r] = 0.f;

        #pragma unroll
        for (int kc = 0; kc < 8; kc++) {
            int k0 = kc * 16;
            uint32_t aq[4], bf[8][2];
            ldsm4(aq[0], aq[1], aq[2], aq[3],
                  qs_b + (qRow * 136 + k0 + qKoff) * 2);
            #pragma unroll
            for (int j = 0; j < 4; j++)
                ldsm4(bf[2 * j][0], bf[2 * j][1], bf[2 * j + 1][0], bf[2 * j + 1][1],
                      ks_b + ((d0 + j * 16 + kOff) * 136 + k0 + kKoff) * 2);
            #pragma unroll
            for (int nb = 0; nb < 8; nb++)
                mma16(S[nb], aq, bf[nb]);
        }

        // ---- online softmax update (warp-private rows, quad shfl only) ----
        float bm0 = -1e30f, bm1 = -1e30f;
        #pragma unroll
        for (int nb = 0; nb < 8; nb++) {
            bm0 = fmaxf(bm0, fmaxf(S[nb][0], S[nb][1]));
            bm1 = fmaxf(bm1, fmaxf(S[nb][2], S[nb][3]));
        }
        #pragma unroll
        for (int o = 1; o <= 2; o <<= 1) {
            bm0 = fmaxf(bm0, __shfl_xor_sync(0xffffffffu, bm0, o));
            bm1 = fmaxf(bm1, __shfl_xor_sync(0xffffffffu, bm1, o));
        }
        float mn0 = fmaxf(mrow0, bm0), mn1 = fmaxf(mrow1, bm1);
        float corr0 = __expf(mrow0 - mn0), corr1 = __expf(mrow1 - mn1);
        mrow0 = mn0; mrow1 = mn1;

        float bs0 = 0.f, bs1 = 0.f;
        #pragma unroll
        for (int nb = 0; nb < 8; nb++) {
            S[nb][0] = __expf(S[nb][0] - mn0);
            S[nb][1] = __expf(S[nb][1] - mn0);
            S[nb][2] = __expf(S[nb][2] - mn1);
            S[nb][3] = __expf(S[nb][3] - mn1);
            bs0 += S[nb][0] + S[nb][1];
            bs1 += S[nb][2] + S[nb][3];
        }
        #pragma unroll
        for (int o = 1; o <= 2; o <<= 1) {
            bs0 += __shfl_xor_sync(0xffffffffu, bs0, o);
            bs1 += __shfl_xor_sync(0xffffffffu, bs1, o);
        }
        lrow0 = lrow0 * corr0 + bs0;
        lrow1 = lrow1 * corr1 + bs1;
        #pragma unroll
        for (int i = 0; i < 16; i++) {
            O[i][0] *= corr0; O[i][1] *= corr0;
            O[i][2] *= corr1; O[i][3] *= corr1;
        }

        if (db == 0) { CP_WAIT0(); __syncthreads(); }   // V now resident

        // ---- GEMM2: O += P_blk @ V[d0..d0+63, :]; P via register A-frags ----
        #pragma unroll
        for (int kc = 0; kc < 4; kc++) {
            // A-frag from S tiles 2kc, 2kc+1 (acc layout == A-frag layout)
            uint32_t pa[4];
            pa[0] = f2h2(S[2 * kc][0],     S[2 * kc][1]);
            pa[1] = f2h2(S[2 * kc][2],     S[2 * kc][3]);
            pa[2] = f2h2(S[2 * kc + 1][0], S[2 * kc + 1][1]);
            pa[3] = f2h2(S[2 * kc + 1][2], S[2 * kc + 1][3]);
            int dr = d0 + kc * 16 + vRow;
            #pragma unroll
            for (int nv = 0; nv < 8; nv++) {
                uint32_t bv[4];
                ldsm4t(bv[0], bv[1], bv[2], bv[3],
                       vs_b + (dr * 136 + nv * 16 + vCol8) * 2);
                uint32_t b0[2] = {bv[0], bv[1]};
                uint32_t b1[2] = {bv[2], bv[3]};
                mma16(O[2 * nv],     pa, b0);
                mma16(O[2 * nv + 1], pa, b1);
            }
        }
    }

    // ---- epilogue: O / l, fp32 store out[b, c, h, w] ----
    float inv0 = 1.f / lrow0, inv1 = 1.f / lrow1;
    int r0 = m0 + g, r1 = m0 + 8 + g;
    #pragma unroll
    for (int nv = 0; nv < 16; nv++) {
        int n = nv * 8 + tg * 2;
        *(float2*)(Og + (size_t)r0 * HWn + n) =
            make_float2(O[nv][0] * inv0, O[nv][1] * inv0);
        *(float2*)(Og + (size_t)r1 * HWn + n) =
            make_float2(O[nv][2] * inv1, O[nv][3] * inv1);
    }
}

// ---------------------------------------------------------------------------
extern "C" void kernel_launch(void* const* d_in, const int* in_sizes, int n_in,
                              void* d_out, int out_size)
{
    (void)in_sizes; (void)n_in; (void)out_size;
    const float* hidden = (const float*)d_in[0];
    const float* ctx    = (const float*)d_in[1];
    const float* qdw = (const float*)d_in[2];
    const float* qdb = (const float*)d_in[3];
    const float* qpw = (const float*)d_in[4];
    const float* qpb = (const float*)d_in[5];
    const float* kdw = (const float*)d_in[6];
    const float* kdb = (const float*)d_in[7];
    const float* kpw = (const float*)d_in[8];
    const float* kpb = (const float*)d_in[9];
    const float* vdw = (const float*)d_in[10];
    const float* vdb = (const float*)d_in[11];
    const float* vpw = (const float*)d_in[12];
    const float* vpb = (const float*)d_in[13];
    float* out = (float*)d_out;

    k_wconv<<<dim3(128, 3), 256>>>(qpw, kpw, vpw);
    k_dwconv<<<dim3(Hn / 16, Bn * Cn), 256>>>(hidden, ctx, qdw, qdb, kdw, kdb, vdw, vdb);

    cudaFuncSetAttribute(k_pointwise, cudaFuncAttributeMaxDynamicSharedMemorySize, PW_SMEM);
    k_pointwise<<<dim3(2, HWn / 128, 24), 256, PW_SMEM>>>(qpb, kpb, vpb);

    cudaFuncSetAttribute(k_attn, cudaFuncAttributeMaxDynamicSharedMemorySize, K3_SMEM);
    k_attn<<<Bn * Hn, 512, K3_SMEM>>>(out);
}